// round 15
// baseline (speedup 1.0000x reference)
#include <cuda_runtime.h>
#include <cuda_bf16.h>
#include <math.h>
#include <stdint.h>

#define SEQ   2048
#define NTOK  4096
#define ED    1024
#define KVD   256
#define HD    128
#define QSC   0.08838834764831845f   // 1/sqrt(128)
#define LOG2E 1.44269504088896340736f

// ---------------- device scratch (no allocations allowed) ----------------
__device__ float g_alpha[4];
__device__ float g_part[4][256];
__device__ __nv_bfloat16 g_wq[ED*ED];
__device__ __nv_bfloat16 g_wk[KVD*ED];
__device__ __nv_bfloat16 g_wv[KVD*ED];
__device__ __nv_bfloat16 g_wo[ED*ED];
__device__ __nv_bfloat16 g_actbf[3*NTOK*ED];   // slot 0:q(=out later) 1:k 2:v
__device__ float g_fact[3*NTOK];
__device__ __nv_bfloat16 g_qhi[NTOK*ED];
__device__ __nv_bfloat16 g_qlo[NTOK*ED];
__device__ __nv_bfloat16 g_khi[NTOK*KVD];
__device__ __nv_bfloat16 g_klo[NTOK*KVD];
__device__ __nv_bfloat16 g_vhi[NTOK*KVD];
__device__ __nv_bfloat16 g_vlo[NTOK*KVD];
__device__ float g_x[NTOK*ED];

__device__ __forceinline__ __nv_bfloat16* sel_w(int m) {
    return m == 0 ? g_wq : m == 1 ? g_wk : m == 2 ? g_wv : g_wo;
}

__device__ __forceinline__ uint32_t smem_u32(const void* p) {
    uint32_t a;
    asm("{ .reg .u64 t; cvta.to.shared.u64 t, %1; cvt.u32.u64 %0, t; }" : "=r"(a) : "l"(p));
    return a;
}
__device__ __forceinline__ unsigned pack_bf2(float a, float b) {
    return (unsigned)__bfloat16_as_ushort(__float2bfloat16_rn(a)) |
           ((unsigned)__bfloat16_as_ushort(__float2bfloat16_rn(b)) << 16);
}

#define LDSM4(R0,R1,R2,R3,ADDR) \
    asm volatile("ldmatrix.sync.aligned.m8n8.x4.shared.b16 {%0,%1,%2,%3}, [%4];" \
        : "=r"(R0), "=r"(R1), "=r"(R2), "=r"(R3) : "r"(ADDR))
#define LDSM4T(R0,R1,R2,R3,ADDR) \
    asm volatile("ldmatrix.sync.aligned.m8n8.x4.trans.shared.b16 {%0,%1,%2,%3}, [%4];" \
        : "=r"(R0), "=r"(R1), "=r"(R2), "=r"(R3) : "r"(ADDR))
#define MMA16816(C, A0,A1,A2,A3, B0,B1) \
    asm volatile("mma.sync.aligned.m16n8k16.row.col.f32.bf16.bf16.f32 " \
        "{%0,%1,%2,%3}, {%4,%5,%6,%7}, {%8,%9}, {%0,%1,%2,%3};" \
        : "+f"((C)[0]), "+f"((C)[1]), "+f"((C)[2]), "+f"((C)[3]) \
        : "r"(A0), "r"(A1), "r"(A2), "r"(A3), "r"(B0), "r"(B1))
#define CP16(SM_, GP_) \
    asm volatile("cp.async.cg.shared.global [%0], [%1], 16;" :: "r"(SM_), "l"(GP_))
#define CPCOMMIT() asm volatile("cp.async.commit_group;" ::: "memory")
#define CPWAIT1()  asm volatile("cp.async.wait_group 1;" ::: "memory")
#define CPWAIT0()  asm volatile("cp.async.wait_group 0;" ::: "memory")

// ---------------- fused weight prep (one launch, grid.y = mid) ----------------
__global__ void prep_w(const float4* __restrict__ w0, const float4* __restrict__ w1,
                       const float4* __restrict__ w2, const float4* __restrict__ w3) {
    __shared__ float sh[256];
    int mid = blockIdx.y;
    const float4* w = mid == 0 ? w0 : mid == 1 ? w1 : mid == 2 ? w2 : w3;
    int n4 = (mid == 1 || mid == 2) ? (KVD * ED / 4) : (ED * ED / 4);
    float s = 0.f;
    uint2* dst = (uint2*)sel_w(mid);
    for (int i = blockIdx.x * 256 + threadIdx.x; i < n4; i += 256 * 256) {
        float4 v = w[i];
        s += fabsf(v.x) + fabsf(v.y) + fabsf(v.z) + fabsf(v.w);
        uint2 c;
        c.x = pack_bf2((float)((v.x > 0.f) - (v.x < 0.f)), (float)((v.y > 0.f) - (v.y < 0.f)));
        c.y = pack_bf2((float)((v.z > 0.f) - (v.z < 0.f)), (float)((v.w > 0.f) - (v.w < 0.f)));
        dst[i] = c;
    }
    sh[threadIdx.x] = s;
    __syncthreads();
    for (int o = 128; o > 0; o >>= 1) {
        if (threadIdx.x < o) sh[threadIdx.x] += sh[threadIdx.x + o];
        __syncthreads();
    }
    if (threadIdx.x == 0) g_part[mid][blockIdx.x] = sh[0];
}

__global__ void absmean_final() {
    int m = blockIdx.x;
    __shared__ float sh[256];
    sh[threadIdx.x] = g_part[m][threadIdx.x];
    __syncthreads();
    for (int o = 128; o > 0; o >>= 1) {
        if (threadIdx.x < o) sh[threadIdx.x] += sh[threadIdx.x + o];
        __syncthreads();
    }
    if (threadIdx.x == 0) {
        float n = (m == 1 || m == 2) ? (float)(KVD * ED) : (float)(ED * ED);
        g_alpha[m] = sh[0] / n;
    }
}

// ---------------- RMSNorm + activation quant: warp-per-token (MLP=8, no barriers) ------
__global__ void __launch_bounds__(256) quant_rms(const float* __restrict__ q,
                                                 const float* __restrict__ k,
                                                 const float* __restrict__ vv) {
    int slot = blockIdx.y;
    const float* x = slot == 0 ? q : slot == 1 ? k : vv;
    int lane = threadIdx.x & 31;
    int tok = blockIdx.x * 8 + (threadIdx.x >> 5);   // 512 blocks x 8 warps = 4096 tokens
    const float4* xr = (const float4*)(x + (size_t)tok * ED);
    float4 v[8];
    #pragma unroll
    for (int i = 0; i < 8; i++) v[i] = xr[lane + i * 32];
    float ss = 0.f, am = 0.f;
    #pragma unroll
    for (int i = 0; i < 8; i++) {
        ss += v[i].x * v[i].x + v[i].y * v[i].y + v[i].z * v[i].z + v[i].w * v[i].w;
        am = fmaxf(am, fmaxf(fmaxf(fabsf(v[i].x), fabsf(v[i].y)),
                             fmaxf(fabsf(v[i].z), fabsf(v[i].w))));
    }
    #pragma unroll
    for (int o = 16; o; o >>= 1) {
        ss += __shfl_xor_sync(0xffffffffu, ss, o);
        am = fmaxf(am, __shfl_xor_sync(0xffffffffu, am, o));
    }
    float r = 1.f / (sqrtf(ss * (1.f / ED) + 1e-6f) * 32.f);
    float scale = 127.f / fmaxf(am * r, 1e-5f);
    if (lane == 0) g_fact[slot * NTOK + tok] = 1.f / scale;
    float f = r * scale;
    uint2* dst = (uint2*)g_actbf + (size_t)slot * NTOK * (ED / 4) + (size_t)tok * (ED / 4);
    #pragma unroll
    for (int i = 0; i < 8; i++) {
        float qx = fminf(fmaxf(rintf(v[i].x * f), -128.f), 127.f);
        float qy = fminf(fmaxf(rintf(v[i].y * f), -128.f), 127.f);
        float qz = fminf(fmaxf(rintf(v[i].z * f), -128.f), 127.f);
        float qw = fminf(fmaxf(rintf(v[i].w * f), -128.f), 127.f);
        uint2 c; c.x = pack_bf2(qx, qy); c.y = pack_bf2(qz, qw);
        dst[lane + i * 32] = c;
    }
}

// ---------------- LayerNorm + RMSNorm + activation quant: warp-per-token ----------------
__global__ void __launch_bounds__(256) ln_quant(const float* __restrict__ g,
                                                const float* __restrict__ bb) {
    int lane = threadIdx.x & 31;
    int tok = blockIdx.x * 8 + (threadIdx.x >> 5);
    const float4* xr = (const float4*)(g_x + (size_t)tok * ED);
    const float4* gg = (const float4*)g;
    const float4* bv = (const float4*)bb;
    float4 v[8];
    float s1 = 0.f, s2 = 0.f;
    #pragma unroll
    for (int i = 0; i < 8; i++) {
        v[i] = xr[lane + i * 32];
        s1 += v[i].x + v[i].y + v[i].z + v[i].w;
        s2 += v[i].x * v[i].x + v[i].y * v[i].y + v[i].z * v[i].z + v[i].w * v[i].w;
    }
    #pragma unroll
    for (int o = 16; o; o >>= 1) {
        s1 += __shfl_xor_sync(0xffffffffu, s1, o);
        s2 += __shfl_xor_sync(0xffffffffu, s2, o);
    }
    float mu = s1 * (1.f / ED);
    float var = fmaxf(s2 * (1.f / ED) - mu * mu, 0.f);
    float inv = rsqrtf(var + 1e-5f);
    float ss = 0.f, am = 0.f;
    #pragma unroll
    for (int i = 0; i < 8; i++) {
        float4 gi = gg[lane + i * 32], bi = bv[lane + i * 32];
        float lx = (v[i].x - mu) * inv * gi.x + bi.x;
        float ly = (v[i].y - mu) * inv * gi.y + bi.y;
        float lz = (v[i].z - mu) * inv * gi.z + bi.z;
        float lw = (v[i].w - mu) * inv * gi.w + bi.w;
        ss += lx * lx + ly * ly + lz * lz + lw * lw;
        am = fmaxf(am, fmaxf(fmaxf(fabsf(lx), fabsf(ly)), fmaxf(fabsf(lz), fabsf(lw))));
    }
    #pragma unroll
    for (int o = 16; o; o >>= 1) {
        ss += __shfl_xor_sync(0xffffffffu, ss, o);
        am = fmaxf(am, __shfl_xor_sync(0xffffffffu, am, o));
    }
    float r = 1.f / (sqrtf(ss * (1.f / ED) + 1e-6f) * 32.f);
    float scale = 127.f / fmaxf(am * r, 1e-5f);
    if (lane == 0) g_fact[tok] = 1.f / scale;
    float f = r * scale;
    uint2* dst = (uint2*)g_actbf + (size_t)tok * (ED / 4);
    #pragma unroll
    for (int i = 0; i < 8; i++) {
        float4 gi = gg[lane + i * 32], bi = bv[lane + i * 32];
        float lx = (v[i].x - mu) * inv * gi.x + bi.x;
        float ly = (v[i].y - mu) * inv * gi.y + bi.y;
        float lz = (v[i].z - mu) * inv * gi.z + bi.z;
        float lw = (v[i].w - mu) * inv * gi.w + bi.w;
        float qx = fminf(fmaxf(rintf(lx * f), -128.f), 127.f);
        float qy = fminf(fmaxf(rintf(ly * f), -128.f), 127.f);
        float qz = fminf(fmaxf(rintf(lz * f), -128.f), 127.f);
        float qw = fminf(fmaxf(rintf(lw * f), -128.f), 127.f);
        uint2 c; c.x = pack_bf2(qx, qy); c.y = pack_bf2(qz, qw);
        dst[lane + i * 32] = c;
    }
}

// ---------------- exact bf16 HMMA GEMM body (R11: LDG+STS double buffer) ----------------
#define GP   72
#define BUFB (128 * GP * 2)
#define GEMM_SMEM (4 * BUFB)

__device__ __forceinline__ void gemm_body(int mid, const float* __restrict__ bias,
                                          int Nout, float* __restrict__ Cext,
                                          int bm, int bn, char* SM) {
    uint32_t sbase = smem_u32(SM);
    int aslot = (mid == 3) ? 0 : mid;
    const __nv_bfloat16* A = g_actbf + (size_t)aslot * NTOK * ED;
    const __nv_bfloat16* B = sel_w(mid);
    int tid = threadIdx.x, wid = tid >> 5, lid = tid & 31;
    int wm = wid & 3, wn = wid >> 2;
    int m0 = bm * 128, n0 = bn * 128;

    auto Aoff = [&](int b) { return (uint32_t)(b * 2 * BUFB); };
    auto Boff = [&](int b) { return (uint32_t)(b * 2 * BUFB + BUFB); };

    int lrow = tid >> 3;
    int lc8  = (tid & 7) * 8;

    {
        const __nv_bfloat16* Ag = A + (size_t)(m0) * ED;
        const __nv_bfloat16* Bg = B + (size_t)(n0) * ED;
        #pragma unroll
        for (int u = 0; u < 4; u++) {
            int row = lrow + u * 32;
            *(uint4*)(SM + Aoff(0) + (row * GP + lc8) * 2) =
                *(const uint4*)(Ag + (size_t)row * ED + lc8);
            *(uint4*)(SM + Boff(0) + (row * GP + lc8) * 2) =
                *(const uint4*)(Bg + (size_t)row * ED + lc8);
        }
    }
    __syncthreads();

    float acc[2][8][4];
    #pragma unroll
    for (int i = 0; i < 2; i++)
        #pragma unroll
        for (int j = 0; j < 8; j++)
            #pragma unroll
            for (int q = 0; q < 4; q++) acc[i][j][q] = 0.f;

    int a_r = lid & 15, a_k8 = (lid >> 4) * 8;
    int b_n = (lid & 7) + ((lid >> 4) & 1) * 8;
    int b_k8 = ((lid >> 3) & 1) * 8;

    #pragma unroll 1
    for (int kt = 0; kt < 16; kt++) {
        int cur = kt & 1;
        uint4 pa[4], pb[4];
        if (kt + 1 < 16) {
            const __nv_bfloat16* Ag = A + (size_t)m0 * ED + (kt + 1) * 64;
            const __nv_bfloat16* Bg = B + (size_t)n0 * ED + (kt + 1) * 64;
            #pragma unroll
            for (int u = 0; u < 4; u++) {
                int row = lrow + u * 32;
                pa[u] = *(const uint4*)(Ag + (size_t)row * ED + lc8);
                pb[u] = *(const uint4*)(Bg + (size_t)row * ED + lc8);
            }
        }
        uint32_t sA = sbase + Aoff(cur), sB = sbase + Boff(cur);
        #pragma unroll
        for (int ks = 0; ks < 4; ks++) {
            uint32_t a[2][4];
            #pragma unroll
            for (int mt = 0; mt < 2; mt++) {
                uint32_t ad = sA + ((wm * 32 + mt * 16 + a_r) * GP + ks * 16 + a_k8) * 2;
                LDSM4(a[mt][0], a[mt][1], a[mt][2], a[mt][3], ad);
            }
            #pragma unroll
            for (int np = 0; np < 4; np++) {
                uint32_t b0, b1, b2, b3;
                uint32_t bd = sB + ((wn * 64 + np * 16 + b_n) * GP + ks * 16 + b_k8) * 2;
                LDSM4(b0, b1, b2, b3, bd);
                MMA16816(acc[0][np * 2 + 0], a[0][0], a[0][1], a[0][2], a[0][3], b0, b1);
                MMA16816(acc[0][np * 2 + 1], a[0][0], a[0][1], a[0][2], a[0][3], b2, b3);
                MMA16816(acc[1][np * 2 + 0], a[1][0], a[1][1], a[1][2], a[1][3], b0, b1);
                MMA16816(acc[1][np * 2 + 1], a[1][0], a[1][1], a[1][2], a[1][3], b2, b3);
            }
        }
        if (kt + 1 < 16) {
            int nxt = cur ^ 1;
            #pragma unroll
            for (int u = 0; u < 4; u++) {
                int row = lrow + u * 32;
                *(uint4*)(SM + Aoff(nxt) + (row * GP + lc8) * 2) = pa[u];
                *(uint4*)(SM + Boff(nxt) + (row * GP + lc8) * 2) = pb[u];
            }
            __syncthreads();
        }
    }

    float alpha = g_alpha[mid];
    float qmul = (mid == 0) ? (QSC * LOG2E) : 1.f;   // fold 1/sqrt(d) * log2(e) into Q
    __nv_bfloat16* Hp = (mid == 0) ? g_qhi : (mid == 1) ? g_khi : g_vhi;
    __nv_bfloat16* Lp = (mid == 0) ? g_qlo : (mid == 1) ? g_klo : g_vlo;
    int trow = lid >> 2, tcol = (lid & 3) * 2;
    #pragma unroll
    for (int mt = 0; mt < 2; mt++) {
        int r0 = m0 + wm * 32 + mt * 16 + trow;
        float sf0 = alpha * qmul * g_fact[aslot * NTOK + r0];
        float sf1 = alpha * qmul * g_fact[aslot * NTOK + r0 + 8];
        #pragma unroll
        for (int nt = 0; nt < 8; nt++) {
            int cc = n0 + wn * 64 + nt * 8 + tcol;
            float bx = bias[cc] * qmul, by = bias[cc + 1] * qmul;
            float c00 = acc[mt][nt][0] * sf0 + bx, c01 = acc[mt][nt][1] * sf0 + by;
            float c10 = acc[mt][nt][2] * sf1 + bx, c11 = acc[mt][nt][3] * sf1 + by;
            if (mid == 3) {
                *(float2*)&Cext[(size_t)r0 * Nout + cc] = make_float2(c00, c01);
                *(float2*)&Cext[(size_t)(r0 + 8) * Nout + cc] = make_float2(c10, c11);
            } else {
                __nv_bfloat16 h00 = __float2bfloat16_rn(c00), h01 = __float2bfloat16_rn(c01);
                __nv_bfloat16 h10 = __float2bfloat16_rn(c10), h11 = __float2bfloat16_rn(c11);
                *(uint*)&Hp[(size_t)r0 * Nout + cc] =
                    (unsigned)__bfloat16_as_ushort(h00) | ((unsigned)__bfloat16_as_ushort(h01) << 16);
                *(uint*)&Hp[(size_t)(r0 + 8) * Nout + cc] =
                    (unsigned)__bfloat16_as_ushort(h10) | ((unsigned)__bfloat16_as_ushort(h11) << 16);
                *(uint*)&Lp[(size_t)r0 * Nout + cc] =
                    pack_bf2(c00 - __bfloat162float(h00), c01 - __bfloat162float(h01));
                *(uint*)&Lp[(size_t)(r0 + 8) * Nout + cc] =
                    pack_bf2(c10 - __bfloat162float(h10), c11 - __bfloat162float(h11));
            }
        }
    }
}

// combined q+k+v projections in one launch (384 CTAs)
__global__ void __launch_bounds__(256) gemm_qkv(const float* __restrict__ qb,
                                                const float* __restrict__ kb,
                                                const float* __restrict__ vb) {
    extern __shared__ char SM[];
    int item = blockIdx.x;
    int mid, bm, bn, Nout;
    const float* bias;
    if (item < 256)      { mid = 0; bias = qb; Nout = ED;  bm = item >> 3;        bn = item & 7; }
    else if (item < 320) { mid = 1; bias = kb; Nout = KVD; bm = (item - 256) >> 1; bn = (item - 256) & 1; }
    else                 { mid = 2; bias = vb; Nout = KVD; bm = (item - 320) >> 1; bn = (item - 320) & 1; }
    gemm_body(mid, bias, Nout, nullptr, bm, bn, SM);
}

__global__ void __launch_bounds__(256) gemm_out(const float* __restrict__ bias,
                                                float* __restrict__ Cext) {
    extern __shared__ char SM[];
    gemm_body(3, bias, ED, Cext, blockIdx.x >> 3, blockIdx.x & 7, SM);
}

// ---------------- HMMA flash attention: R11 3-stage cp.async, 1 barrier/iter ----------------
#define VP 136
#define BUF_ELE (256 * VP)
#define ATTN_SMEM (3 * BUF_ELE * 2)        // 208896 B

__global__ void __launch_bounds__(256, 1) attn_mma() {
    extern __shared__ __nv_bfloat16 SB[];
    uint32_t sbase = smem_u32(SB);
    int tid = threadIdx.x, wid = tid >> 5, lid = tid & 31;
    int qt = blockIdx.x, bh = blockIdx.y;
    int b = bh >> 3, h = bh & 7, kvh = h >> 2;
    const __nv_bfloat16* qhig = g_qhi + ((size_t)b * SEQ + qt * 128) * ED + h * HD;
    const __nv_bfloat16* qlog = g_qlo + ((size_t)b * SEQ + qt * 128) * ED + h * HD;
    const __nv_bfloat16* khig = g_khi + (size_t)b * SEQ * KVD + kvh * HD;
    const __nv_bfloat16* klog = g_klo + (size_t)b * SEQ * KVD + kvh * HD;
    const __nv_bfloat16* vhig = g_vhi + (size_t)b * SEQ * KVD + kvh * HD;
    const __nv_bfloat16* vlog = g_vlo + (size_t)b * SEQ * KVD + kvh * HD;

    auto issue = [&](int kt, int buf) {
        uint32_t sb0 = sbase + (uint32_t)(buf * BUF_ELE) * 2;
        #pragma unroll
        for (int sec = 0; sec < 4; sec++) {
            const __nv_bfloat16* gb = (sec == 0) ? khig : (sec == 1) ? klog
                                     : (sec == 2) ? vhig : vlog;
            #pragma unroll
            for (int u = 0; u < 4; u++) {
                int jj = tid + u * 256;
                int row = jj >> 4, c8 = (jj & 15) * 8;
                const __nv_bfloat16* gp = gb + (size_t)(kt * 64 + row) * KVD + c8;
                uint32_t sm = sb0 + (uint32_t)((sec * 64 + row) * VP + c8) * 2;
                CP16(sm, gp);
            }
        }
    };

    // ---- stage Q into buffer 2; start tiles 0,1 into buffers 0,1 ----
    #pragma unroll
    for (int u = 0; u < 8; u++) {
        int i = tid + u * 256;
        int row = i >> 4, c8 = (i & 15) * 8;
        *(uint4*)&SB[2 * BUF_ELE + row * VP + c8] = *(const uint4*)(qhig + (size_t)row * ED + c8);
        *(uint4*)&SB[2 * BUF_ELE + (128 + row) * VP + c8] = *(const uint4*)(qlog + (size_t)row * ED + c8);
    }
    issue(0, 0);
    CPCOMMIT();
    issue(1, 1);
    CPCOMMIT();
    __syncthreads();

    // ---- Q fragments to registers (from buffer 2) ----
    uint32_t qh[8][4], ql[8][4];
    {
        int ar = lid & 15, ak8 = (lid >> 4) * 8;
        #pragma unroll
        for (int j = 0; j < 8; j++) {
            uint32_t adh = sbase + (uint32_t)(2 * BUF_ELE + (wid * 16 + ar) * VP + j * 16 + ak8) * 2;
            LDSM4(qh[j][0], qh[j][1], qh[j][2], qh[j][3], adh);
            uint32_t adl = sbase + (uint32_t)(2 * BUF_ELE + (128 + wid * 16 + ar) * VP + j * 16 + ak8) * 2;
            LDSM4(ql[j][0], ql[j][1], ql[j][2], ql[j][3], adl);
        }
    }
    __syncthreads();   // buffer 2 free for tile 2 (issued at iter 0)

    float m_[2] = {-1e30f, -1e30f}, l_[2] = {0.f, 0.f};
    float o[16][4];
    #pragma unroll
    for (int i = 0; i < 16; i++)
        #pragma unroll
        for (int q = 0; q < 4; q++) o[i][q] = 0.f;

    int b_n  = (lid & 7) + ((lid >> 4) & 1) * 8;
    int b_k8 = ((lid >> 3) & 1) * 8;
    int v_r  = lid & 15, v_n8 = (lid >> 4) * 8;

    int cur = 0, nx2 = 2;   // cur = kt%3, nx2 = (kt+2)%3
    #pragma unroll 1
    for (int kt = 0; kt < 32; kt++) {
        if (kt < 31) { CPWAIT1(); } else { CPWAIT0(); }
        __syncthreads();
        if (kt + 2 < 32) { issue(kt + 2, nx2); CPCOMMIT(); }

        uint32_t kb = (uint32_t)(cur * BUF_ELE);
        uint32_t sKH = kb, sKL = kb + 64 * VP, sVH = kb + 128 * VP, sVL = kb + 192 * VP;

        float S[8][4];
        #pragma unroll
        for (int nt = 0; nt < 8; nt++)
            #pragma unroll
            for (int q = 0; q < 4; q++) S[nt][q] = 0.f;
        #pragma unroll
        for (int j = 0; j < 8; j++) {
            #pragma unroll
            for (int g = 0; g < 4; g++) {
                uint32_t bh0, bh1, bh2, bh3, bl0, bl1, bl2, bl3;
                uint32_t adh = sbase + (uint32_t)(sKH + (g * 16 + b_n) * VP + j * 16 + b_k8) * 2;
                LDSM4(bh0, bh1, bh2, bh3, adh);
                uint32_t adl = sbase + (uint32_t)(sKL + (g * 16 + b_n) * VP + j * 16 + b_k8) * 2;
                LDSM4(bl0, bl1, bl2, bl3, adl);
                MMA16816(S[2*g],   qh[j][0], qh[j][1], qh[j][2], qh[j][3], bh0, bh1);
                MMA16816(S[2*g],   qh[j][0], qh[j][1], qh[j][2], qh[j][3], bl0, bl1);
                MMA16816(S[2*g],   ql[j][0], ql[j][1], ql[j][2], ql[j][3], bh0, bh1);
                MMA16816(S[2*g+1], qh[j][0], qh[j][1], qh[j][2], qh[j][3], bh2, bh3);
                MMA16816(S[2*g+1], qh[j][0], qh[j][1], qh[j][2], qh[j][3], bl2, bl3);
                MMA16816(S[2*g+1], ql[j][0], ql[j][1], ql[j][2], ql[j][3], bh2, bh3);
            }
        }

        // ---- online softmax (exp2 domain; Q pre-scaled by log2e) with skip-rescale ----
        #pragma unroll
        for (int rr = 0; rr < 2; rr++) {
            int c0 = rr * 2;
            float mx = -1e30f;
            #pragma unroll
            for (int nt = 0; nt < 8; nt++)
                mx = fmaxf(mx, fmaxf(S[nt][c0], S[nt][c0 + 1]));
            mx = fmaxf(mx, __shfl_xor_sync(0xffffffffu, mx, 1));
            mx = fmaxf(mx, __shfl_xor_sync(0xffffffffu, mx, 2));
            if (mx > m_[rr]) {
                float corr = exp2f(m_[rr] - mx);
                m_[rr] = mx;
                l_[rr] *= corr;
                #pragma unroll
                for (int nt = 0; nt < 16; nt++) {
                    o[nt][c0] *= corr; o[nt][c0 + 1] *= corr;
                }
            }
            float mn = m_[rr];
            float sum = 0.f;
            #pragma unroll
            for (int nt = 0; nt < 8; nt++) {
                float p0 = exp2f(S[nt][c0] - mn);
                float p1 = exp2f(S[nt][c0 + 1] - mn);
                S[nt][c0] = p0; S[nt][c0 + 1] = p1;
                sum += p0 + p1;
            }
            sum += __shfl_xor_sync(0xffffffffu, sum, 1);
            sum += __shfl_xor_sync(0xffffffffu, sum, 2);
            l_[rr] += sum;
        }

        uint32_t ph[4][4], pl[4][4];
        #pragma unroll
        for (int jp = 0; jp < 4; jp++) {
            #pragma unroll
            for (int q = 0; q < 4; q++) {
                int nt = 2 * jp + (q >> 1);
                int c0 = (q & 1) * 2;
                float x = S[nt][c0], y = S[nt][c0 + 1];
                __nv_bfloat16 hx = __float2bfloat16_rn(x);
                __nv_bfloat16 hy = __float2bfloat16_rn(y);
                ph[jp][q] = (unsigned)__bfloat16_as_ushort(hx) |
                            ((unsigned)__bfloat16_as_ushort(hy) << 16);
                pl[jp][q] = pack_bf2(x - __bfloat162float(hx), y - __bfloat162float(hy));
            }
        }

        #pragma unroll
        for (int jp = 0; jp < 4; jp++) {
            #pragma unroll
            for (int g = 0; g < 8; g++) {
                uint32_t vh0, vh1, vh2, vh3, vl0, vl1, vl2, vl3;
                uint32_t adh = sbase + (uint32_t)(sVH + (jp * 16 + v_r) * VP + g * 16 + v_n8) * 2;
                LDSM4T(vh0, vh1, vh2, vh3, adh);
                uint32_t adl = sbase + (uint32_t)(sVL + (jp * 16 + v_r) * VP + g * 16 + v_n8) * 2;
                LDSM4T(vl0, vl1, vl2, vl3, adl);
                MMA16816(o[2*g],   ph[jp][0], ph[jp][1], ph[jp][2], ph[jp][3], vh0, vh1);
                MMA16816(o[2*g],   ph[jp][0], ph[jp][1], ph[jp][2], ph[jp][3], vl0, vl1);
                MMA16816(o[2*g],   pl[jp][0], pl[jp][1], pl[jp][2], pl[jp][3], vh0, vh1);
                MMA16816(o[2*g+1], ph[jp][0], ph[jp][1], ph[jp][2], ph[jp][3], vh2, vh3);
                MMA16816(o[2*g+1], ph[jp][0], ph[jp][1], ph[jp][2], ph[jp][3], vl2, vl3);
                MMA16816(o[2*g+1], pl[jp][0], pl[jp][1], pl[jp][2], pl[jp][3], vh2, vh3);
            }
        }

        cur = (cur == 2) ? 0 : cur + 1;
        nx2 = (nx2 == 2) ? 0 : nx2 + 1;
    }

    #pragma unroll
    for (int rr = 0; rr < 2; rr++) {
        float inv = 1.f / l_[rr];
        int srow = qt * 128 + wid * 16 + (lid >> 2) + rr * 8;
        float* xo = g_x + ((size_t)b * SEQ + srow) * ED + h * HD;
        #pragma unroll
        for (int nt = 0; nt < 16; nt++) {
            int col = nt * 8 + (lid & 3) * 2;
            *(float2*)&xo[col] = make_float2(o[nt][rr * 2] * inv, o[nt][rr * 2 + 1] * inv);
        }
    }
}

// ---------------- launch ----------------
extern "C" void kernel_launch(void* const* d_in, const int* in_sizes, int n_in,
                              void* d_out, int out_size) {
    const float* query = (const float*)d_in[0];
    const float* key   = (const float*)d_in[1];
    const float* value = (const float*)d_in[2];
    const float* q_w   = (const float*)d_in[3];
    const float* q_b   = (const float*)d_in[4];
    const float* k_w   = (const float*)d_in[5];
    const float* k_b   = (const float*)d_in[6];
    const float* v_w   = (const float*)d_in[7];
    const float* v_b   = (const float*)d_in[8];
    const float* ln_g  = (const float*)d_in[9];
    const float* ln_b  = (const float*)d_in[10];
    const float* out_w = (const float*)d_in[11];
    const float* out_b = (const float*)d_in[12];

    // one-time resources (created on the pre-capture correctness call)
    static cudaStream_t s2 = nullptr;
    static cudaEvent_t evFork = nullptr, evJoin = nullptr;
    if (s2 == nullptr) {
        cudaStreamCreateWithFlags(&s2, cudaStreamNonBlocking);
        cudaEventCreateWithFlags(&evFork, cudaEventDisableTiming);
        cudaEventCreateWithFlags(&evJoin, cudaEventDisableTiming);
        cudaFuncSetAttribute(attn_mma, cudaFuncAttributeMaxDynamicSharedMemorySize, ATTN_SMEM);
        cudaFuncSetAttribute(gemm_qkv, cudaFuncAttributeMaxDynamicSharedMemorySize, GEMM_SMEM);
        cudaFuncSetAttribute(gemm_out, cudaFuncAttributeMaxDynamicSharedMemorySize, GEMM_SMEM);
    }

    // fork: weight prep on s2, activation quant on main stream (independent)
    cudaEventRecord(evFork, 0);
    cudaStreamWaitEvent(s2, evFork, 0);
    prep_w<<<dim3(256, 4), 256, 0, s2>>>((const float4*)q_w, (const float4*)k_w,
                                         (const float4*)v_w, (const float4*)out_w);
    absmean_final<<<4, 256, 0, s2>>>();
    cudaEventRecord(evJoin, s2);

    quant_rms<<<dim3(NTOK / 8, 3), 256>>>(query, key, value);

    // join: projections need both branches
    cudaStreamWaitEvent(0, evJoin, 0);
    gemm_qkv<<<384, 256, GEMM_SMEM>>>(q_b, k_b, v_b);

    // attention (HMMA split-bf16, exp2 softmax, 3-stage pipeline)
    attn_mma<<<dim3(SEQ / 128, 16), 256, ATTN_SMEM>>>();

    // layernorm + final bitlinear
    ln_quant<<<NTOK / 8, 256>>>(ln_g, ln_b);
    gemm_out<<<256, 256, GEMM_SMEM>>>(out_b, (float*)d_out);
}

// round 16
// speedup vs baseline: 1.0219x; 1.0219x over previous
#include <cuda_runtime.h>
#include <cuda_bf16.h>
#include <math.h>
#include <stdint.h>

#define SEQ   2048
#define NTOK  4096
#define ED    1024
#define KVD   256
#define HD    128
#define QSC   0.08838834764831845f   // 1/sqrt(128)
#define LOG2E 1.44269504088896340736f
#define NSPLIT 4
#define TPS    8                      // KV tiles per split (32/NSPLIT)

// ---------------- device scratch (no allocations allowed) ----------------
__device__ float g_alpha[4];
__device__ float g_part[4][256];
__device__ __nv_bfloat16 g_wq[ED*ED];
__device__ __nv_bfloat16 g_wk[KVD*ED];
__device__ __nv_bfloat16 g_wv[KVD*ED];
__device__ __nv_bfloat16 g_wo[ED*ED];
__device__ __nv_bfloat16 g_actbf[3*NTOK*ED];   // slot 0:q(=out later) 1:k 2:v
__device__ float g_fact[3*NTOK];
__device__ __nv_bfloat16 g_qhi[NTOK*ED];
__device__ __nv_bfloat16 g_qlo[NTOK*ED];
__device__ __nv_bfloat16 g_khi[NTOK*KVD];
__device__ __nv_bfloat16 g_klo[NTOK*KVD];
__device__ __nv_bfloat16 g_vhi[NTOK*KVD];
__device__ __nv_bfloat16 g_vlo[NTOK*KVD];
__device__ float g_x[NTOK*ED];
// split-KV attention partials: [split][bh][qt][...]
__device__ float g_po[NSPLIT][16][16][128*128];
__device__ float g_pm[NSPLIT][16][16][128];
__device__ float g_pl[NSPLIT][16][16][128];

__device__ __forceinline__ __nv_bfloat16* sel_w(int m) {
    return m == 0 ? g_wq : m == 1 ? g_wk : m == 2 ? g_wv : g_wo;
}

__device__ __forceinline__ uint32_t smem_u32(const void* p) {
    uint32_t a;
    asm("{ .reg .u64 t; cvta.to.shared.u64 t, %1; cvt.u32.u64 %0, t; }" : "=r"(a) : "l"(p));
    return a;
}
__device__ __forceinline__ unsigned pack_bf2(float a, float b) {
    return (unsigned)__bfloat16_as_ushort(__float2bfloat16_rn(a)) |
           ((unsigned)__bfloat16_as_ushort(__float2bfloat16_rn(b)) << 16);
}

#define LDSM4(R0,R1,R2,R3,ADDR) \
    asm volatile("ldmatrix.sync.aligned.m8n8.x4.shared.b16 {%0,%1,%2,%3}, [%4];" \
        : "=r"(R0), "=r"(R1), "=r"(R2), "=r"(R3) : "r"(ADDR))
#define LDSM4T(R0,R1,R2,R3,ADDR) \
    asm volatile("ldmatrix.sync.aligned.m8n8.x4.trans.shared.b16 {%0,%1,%2,%3}, [%4];" \
        : "=r"(R0), "=r"(R1), "=r"(R2), "=r"(R3) : "r"(ADDR))
#define MMA16816(C, A0,A1,A2,A3, B0,B1) \
    asm volatile("mma.sync.aligned.m16n8k16.row.col.f32.bf16.bf16.f32 " \
        "{%0,%1,%2,%3}, {%4,%5,%6,%7}, {%8,%9}, {%0,%1,%2,%3};" \
        : "+f"((C)[0]), "+f"((C)[1]), "+f"((C)[2]), "+f"((C)[3]) \
        : "r"(A0), "r"(A1), "r"(A2), "r"(A3), "r"(B0), "r"(B1))
#define CP16(SM_, GP_) \
    asm volatile("cp.async.cg.shared.global [%0], [%1], 16;" :: "r"(SM_), "l"(GP_))
#define CPCOMMIT() asm volatile("cp.async.commit_group;" ::: "memory")
#define CPWAIT1()  asm volatile("cp.async.wait_group 1;" ::: "memory")
#define CPWAIT0()  asm volatile("cp.async.wait_group 0;" ::: "memory")

// ---------------- fused weight prep (one launch, grid.y = mid) ----------------
__global__ void prep_w(const float4* __restrict__ w0, const float4* __restrict__ w1,
                       const float4* __restrict__ w2, const float4* __restrict__ w3) {
    __shared__ float sh[256];
    int mid = blockIdx.y;
    const float4* w = mid == 0 ? w0 : mid == 1 ? w1 : mid == 2 ? w2 : w3;
    int n4 = (mid == 1 || mid == 2) ? (KVD * ED / 4) : (ED * ED / 4);
    float s = 0.f;
    uint2* dst = (uint2*)sel_w(mid);
    for (int i = blockIdx.x * 256 + threadIdx.x; i < n4; i += 256 * 256) {
        float4 v = w[i];
        s += fabsf(v.x) + fabsf(v.y) + fabsf(v.z) + fabsf(v.w);
        uint2 c;
        c.x = pack_bf2((float)((v.x > 0.f) - (v.x < 0.f)), (float)((v.y > 0.f) - (v.y < 0.f)));
        c.y = pack_bf2((float)((v.z > 0.f) - (v.z < 0.f)), (float)((v.w > 0.f) - (v.w < 0.f)));
        dst[i] = c;
    }
    sh[threadIdx.x] = s;
    __syncthreads();
    for (int o = 128; o > 0; o >>= 1) {
        if (threadIdx.x < o) sh[threadIdx.x] += sh[threadIdx.x + o];
        __syncthreads();
    }
    if (threadIdx.x == 0) g_part[mid][blockIdx.x] = sh[0];
}

__global__ void absmean_final() {
    int m = blockIdx.x;
    __shared__ float sh[256];
    sh[threadIdx.x] = g_part[m][threadIdx.x];
    __syncthreads();
    for (int o = 128; o > 0; o >>= 1) {
        if (threadIdx.x < o) sh[threadIdx.x] += sh[threadIdx.x + o];
        __syncthreads();
    }
    if (threadIdx.x == 0) {
        float n = (m == 1 || m == 2) ? (float)(KVD * ED) : (float)(ED * ED);
        g_alpha[m] = sh[0] / n;
    }
}

// ---------------- RMSNorm + activation quant: warp-per-token ----------------
__global__ void __launch_bounds__(256) quant_rms(const float* __restrict__ q,
                                                 const float* __restrict__ k,
                                                 const float* __restrict__ vv) {
    int slot = blockIdx.y;
    const float* x = slot == 0 ? q : slot == 1 ? k : vv;
    int lane = threadIdx.x & 31;
    int tok = blockIdx.x * 8 + (threadIdx.x >> 5);
    const float4* xr = (const float4*)(x + (size_t)tok * ED);
    float4 v[8];
    #pragma unroll
    for (int i = 0; i < 8; i++) v[i] = xr[lane + i * 32];
    float ss = 0.f, am = 0.f;
    #pragma unroll
    for (int i = 0; i < 8; i++) {
        ss += v[i].x * v[i].x + v[i].y * v[i].y + v[i].z * v[i].z + v[i].w * v[i].w;
        am = fmaxf(am, fmaxf(fmaxf(fabsf(v[i].x), fabsf(v[i].y)),
                             fmaxf(fabsf(v[i].z), fabsf(v[i].w))));
    }
    #pragma unroll
    for (int o = 16; o; o >>= 1) {
        ss += __shfl_xor_sync(0xffffffffu, ss, o);
        am = fmaxf(am, __shfl_xor_sync(0xffffffffu, am, o));
    }
    float r = 1.f / (sqrtf(ss * (1.f / ED) + 1e-6f) * 32.f);
    float scale = 127.f / fmaxf(am * r, 1e-5f);
    if (lane == 0) g_fact[slot * NTOK + tok] = 1.f / scale;
    float f = r * scale;
    uint2* dst = (uint2*)g_actbf + (size_t)slot * NTOK * (ED / 4) + (size_t)tok * (ED / 4);
    #pragma unroll
    for (int i = 0; i < 8; i++) {
        float qx = fminf(fmaxf(rintf(v[i].x * f), -128.f), 127.f);
        float qy = fminf(fmaxf(rintf(v[i].y * f), -128.f), 127.f);
        float qz = fminf(fmaxf(rintf(v[i].z * f), -128.f), 127.f);
        float qw = fminf(fmaxf(rintf(v[i].w * f), -128.f), 127.f);
        uint2 c; c.x = pack_bf2(qx, qy); c.y = pack_bf2(qz, qw);
        dst[lane + i * 32] = c;
    }
}

// ---------------- LayerNorm + RMSNorm + activation quant: warp-per-token ----------------
__global__ void __launch_bounds__(256) ln_quant(const float* __restrict__ g,
                                                const float* __restrict__ bb) {
    int lane = threadIdx.x & 31;
    int tok = blockIdx.x * 8 + (threadIdx.x >> 5);
    const float4* xr = (const float4*)(g_x + (size_t)tok * ED);
    const float4* gg = (const float4*)g;
    const float4* bv = (const float4*)bb;
    float4 v[8];
    float s1 = 0.f, s2 = 0.f;
    #pragma unroll
    for (int i = 0; i < 8; i++) {
        v[i] = xr[lane + i * 32];
        s1 += v[i].x + v[i].y + v[i].z + v[i].w;
        s2 += v[i].x * v[i].x + v[i].y * v[i].y + v[i].z * v[i].z + v[i].w * v[i].w;
    }
    #pragma unroll
    for (int o = 16; o; o >>= 1) {
        s1 += __shfl_xor_sync(0xffffffffu, s1, o);
        s2 += __shfl_xor_sync(0xffffffffu, s2, o);
    }
    float mu = s1 * (1.f / ED);
    float var = fmaxf(s2 * (1.f / ED) - mu * mu, 0.f);
    float inv = rsqrtf(var + 1e-5f);
    float ss = 0.f, am = 0.f;
    #pragma unroll
    for (int i = 0; i < 8; i++) {
        float4 gi = gg[lane + i * 32], bi = bv[lane + i * 32];
        float lx = (v[i].x - mu) * inv * gi.x + bi.x;
        float ly = (v[i].y - mu) * inv * gi.y + bi.y;
        float lz = (v[i].z - mu) * inv * gi.z + bi.z;
        float lw = (v[i].w - mu) * inv * gi.w + bi.w;
        ss += lx * lx + ly * ly + lz * lz + lw * lw;
        am = fmaxf(am, fmaxf(fmaxf(fabsf(lx), fabsf(ly)), fmaxf(fabsf(lz), fabsf(lw))));
    }
    #pragma unroll
    for (int o = 16; o; o >>= 1) {
        ss += __shfl_xor_sync(0xffffffffu, ss, o);
        am = fmaxf(am, __shfl_xor_sync(0xffffffffu, am, o));
    }
    float r = 1.f / (sqrtf(ss * (1.f / ED) + 1e-6f) * 32.f);
    float scale = 127.f / fmaxf(am * r, 1e-5f);
    if (lane == 0) g_fact[tok] = 1.f / scale;
    float f = r * scale;
    uint2* dst = (uint2*)g_actbf + (size_t)tok * (ED / 4);
    #pragma unroll
    for (int i = 0; i < 8; i++) {
        float4 gi = gg[lane + i * 32], bi = bv[lane + i * 32];
        float lx = (v[i].x - mu) * inv * gi.x + bi.x;
        float ly = (v[i].y - mu) * inv * gi.y + bi.y;
        float lz = (v[i].z - mu) * inv * gi.z + bi.z;
        float lw = (v[i].w - mu) * inv * gi.w + bi.w;
        float qx = fminf(fmaxf(rintf(lx * f), -128.f), 127.f);
        float qy = fminf(fmaxf(rintf(ly * f), -128.f), 127.f);
        float qz = fminf(fmaxf(rintf(lz * f), -128.f), 127.f);
        float qw = fminf(fmaxf(rintf(lw * f), -128.f), 127.f);
        uint2 c; c.x = pack_bf2(qx, qy); c.y = pack_bf2(qz, qw);
        dst[lane + i * 32] = c;
    }
}

// ---------------- exact bf16 HMMA GEMM body (R11: LDG+STS double buffer) ----------------
#define GP   72
#define BUFB (128 * GP * 2)
#define GEMM_SMEM (4 * BUFB)

__device__ __forceinline__ void gemm_body(int mid, const float* __restrict__ bias,
                                          int Nout, float* __restrict__ Cext,
                                          int bm, int bn, char* SM) {
    uint32_t sbase = smem_u32(SM);
    int aslot = (mid == 3) ? 0 : mid;
    const __nv_bfloat16* A = g_actbf + (size_t)aslot * NTOK * ED;
    const __nv_bfloat16* B = sel_w(mid);
    int tid = threadIdx.x, wid = tid >> 5, lid = tid & 31;
    int wm = wid & 3, wn = wid >> 2;
    int m0 = bm * 128, n0 = bn * 128;

    auto Aoff = [&](int b) { return (uint32_t)(b * 2 * BUFB); };
    auto Boff = [&](int b) { return (uint32_t)(b * 2 * BUFB + BUFB); };

    int lrow = tid >> 3;
    int lc8  = (tid & 7) * 8;

    {
        const __nv_bfloat16* Ag = A + (size_t)(m0) * ED;
        const __nv_bfloat16* Bg = B + (size_t)(n0) * ED;
        #pragma unroll
        for (int u = 0; u < 4; u++) {
            int row = lrow + u * 32;
            *(uint4*)(SM + Aoff(0) + (row * GP + lc8) * 2) =
                *(const uint4*)(Ag + (size_t)row * ED + lc8);
            *(uint4*)(SM + Boff(0) + (row * GP + lc8) * 2) =
                *(const uint4*)(Bg + (size_t)row * ED + lc8);
        }
    }
    __syncthreads();

    float acc[2][8][4];
    #pragma unroll
    for (int i = 0; i < 2; i++)
        #pragma unroll
        for (int j = 0; j < 8; j++)
            #pragma unroll
            for (int q = 0; q < 4; q++) acc[i][j][q] = 0.f;

    int a_r = lid & 15, a_k8 = (lid >> 4) * 8;
    int b_n = (lid & 7) + ((lid >> 4) & 1) * 8;
    int b_k8 = ((lid >> 3) & 1) * 8;

    #pragma unroll 1
    for (int kt = 0; kt < 16; kt++) {
        int cur = kt & 1;
        uint4 pa[4], pb[4];
        if (kt + 1 < 16) {
            const __nv_bfloat16* Ag = A + (size_t)m0 * ED + (kt + 1) * 64;
            const __nv_bfloat16* Bg = B + (size_t)n0 * ED + (kt + 1) * 64;
            #pragma unroll
            for (int u = 0; u < 4; u++) {
                int row = lrow + u * 32;
                pa[u] = *(const uint4*)(Ag + (size_t)row * ED + lc8);
                pb[u] = *(const uint4*)(Bg + (size_t)row * ED + lc8);
            }
        }
        uint32_t sA = sbase + Aoff(cur), sB = sbase + Boff(cur);
        #pragma unroll
        for (int ks = 0; ks < 4; ks++) {
            uint32_t a[2][4];
            #pragma unroll
            for (int mt = 0; mt < 2; mt++) {
                uint32_t ad = sA + ((wm * 32 + mt * 16 + a_r) * GP + ks * 16 + a_k8) * 2;
                LDSM4(a[mt][0], a[mt][1], a[mt][2], a[mt][3], ad);
            }
            #pragma unroll
            for (int np = 0; np < 4; np++) {
                uint32_t b0, b1, b2, b3;
                uint32_t bd = sB + ((wn * 64 + np * 16 + b_n) * GP + ks * 16 + b_k8) * 2;
                LDSM4(b0, b1, b2, b3, bd);
                MMA16816(acc[0][np * 2 + 0], a[0][0], a[0][1], a[0][2], a[0][3], b0, b1);
                MMA16816(acc[0][np * 2 + 1], a[0][0], a[0][1], a[0][2], a[0][3], b2, b3);
                MMA16816(acc[1][np * 2 + 0], a[1][0], a[1][1], a[1][2], a[1][3], b0, b1);
                MMA16816(acc[1][np * 2 + 1], a[1][0], a[1][1], a[1][2], a[1][3], b2, b3);
            }
        }
        if (kt + 1 < 16) {
            int nxt = cur ^ 1;
            #pragma unroll
            for (int u = 0; u < 4; u++) {
                int row = lrow + u * 32;
                *(uint4*)(SM + Aoff(nxt) + (row * GP + lc8) * 2) = pa[u];
                *(uint4*)(SM + Boff(nxt) + (row * GP + lc8) * 2) = pb[u];
            }
            __syncthreads();
        }
    }

    float alpha = g_alpha[mid];
    float qmul = (mid == 0) ? (QSC * LOG2E) : 1.f;
    __nv_bfloat16* Hp = (mid == 0) ? g_qhi : (mid == 1) ? g_khi : g_vhi;
    __nv_bfloat16* Lp = (mid == 0) ? g_qlo : (mid == 1) ? g_klo : g_vlo;
    int trow = lid >> 2, tcol = (lid & 3) * 2;
    #pragma unroll
    for (int mt = 0; mt < 2; mt++) {
        int r0 = m0 + wm * 32 + mt * 16 + trow;
        float sf0 = alpha * qmul * g_fact[aslot * NTOK + r0];
        float sf1 = alpha * qmul * g_fact[aslot * NTOK + r0 + 8];
        #pragma unroll
        for (int nt = 0; nt < 8; nt++) {
            int cc = n0 + wn * 64 + nt * 8 + tcol;
            float bx = bias[cc] * qmul, by = bias[cc + 1] * qmul;
            float c00 = acc[mt][nt][0] * sf0 + bx, c01 = acc[mt][nt][1] * sf0 + by;
            float c10 = acc[mt][nt][2] * sf1 + bx, c11 = acc[mt][nt][3] * sf1 + by;
            if (mid == 3) {
                *(float2*)&Cext[(size_t)r0 * Nout + cc] = make_float2(c00, c01);
                *(float2*)&Cext[(size_t)(r0 + 8) * Nout + cc] = make_float2(c10, c11);
            } else {
                __nv_bfloat16 h00 = __float2bfloat16_rn(c00), h01 = __float2bfloat16_rn(c01);
                __nv_bfloat16 h10 = __float2bfloat16_rn(c10), h11 = __float2bfloat16_rn(c11);
                *(uint*)&Hp[(size_t)r0 * Nout + cc] =
                    (unsigned)__bfloat16_as_ushort(h00) | ((unsigned)__bfloat16_as_ushort(h01) << 16);
                *(uint*)&Hp[(size_t)(r0 + 8) * Nout + cc] =
                    (unsigned)__bfloat16_as_ushort(h10) | ((unsigned)__bfloat16_as_ushort(h11) << 16);
                *(uint*)&Lp[(size_t)r0 * Nout + cc] =
                    pack_bf2(c00 - __bfloat162float(h00), c01 - __bfloat162float(h01));
                *(uint*)&Lp[(size_t)(r0 + 8) * Nout + cc] =
                    pack_bf2(c10 - __bfloat162float(h10), c11 - __bfloat162float(h11));
            }
        }
    }
}

__global__ void __launch_bounds__(256) gemm_qkv(const float* __restrict__ qb,
                                                const float* __restrict__ kb,
                                                const float* __restrict__ vb) {
    extern __shared__ char SM[];
    int item = blockIdx.x;
    int mid, bm, bn, Nout;
    const float* bias;
    if (item < 256)      { mid = 0; bias = qb; Nout = ED;  bm = item >> 3;        bn = item & 7; }
    else if (item < 320) { mid = 1; bias = kb; Nout = KVD; bm = (item - 256) >> 1; bn = (item - 256) & 1; }
    else                 { mid = 2; bias = vb; Nout = KVD; bm = (item - 320) >> 1; bn = (item - 320) & 1; }
    gemm_body(mid, bias, Nout, nullptr, bm, bn, SM);
}

__global__ void __launch_bounds__(256) gemm_out(const float* __restrict__ bias,
                                                float* __restrict__ Cext) {
    extern __shared__ char SM[];
    gemm_body(3, bias, ED, Cext, blockIdx.x >> 3, blockIdx.x & 7, SM);
}

// ---------------- HMMA flash attention: split-KV x4, 3-stage cp.async ----------------
#define VP 136
#define BUF_ELE (256 * VP)
#define ATTN_SMEM (3 * BUF_ELE * 2)        // 208896 B

__global__ void __launch_bounds__(256, 1) attn_mma() {
    extern __shared__ __nv_bfloat16 SB[];
    uint32_t sbase = smem_u32(SB);
    int tid = threadIdx.x, wid = tid >> 5, lid = tid & 31;
    int qt = blockIdx.x, bh = blockIdx.y, split = blockIdx.z;
    int b = bh >> 3, h = bh & 7, kvh = h >> 2;
    int t0 = split * TPS;
    const __nv_bfloat16* qhig = g_qhi + ((size_t)b * SEQ + qt * 128) * ED + h * HD;
    const __nv_bfloat16* qlog = g_qlo + ((size_t)b * SEQ + qt * 128) * ED + h * HD;
    const __nv_bfloat16* khig = g_khi + (size_t)b * SEQ * KVD + kvh * HD;
    const __nv_bfloat16* klog = g_klo + (size_t)b * SEQ * KVD + kvh * HD;
    const __nv_bfloat16* vhig = g_vhi + (size_t)b * SEQ * KVD + kvh * HD;
    const __nv_bfloat16* vlog = g_vlo + (size_t)b * SEQ * KVD + kvh * HD;

    auto issue = [&](int kt, int buf) {
        uint32_t sb0 = sbase + (uint32_t)(buf * BUF_ELE) * 2;
        #pragma unroll
        for (int sec = 0; sec < 4; sec++) {
            const __nv_bfloat16* gb = (sec == 0) ? khig : (sec == 1) ? klog
                                     : (sec == 2) ? vhig : vlog;
            #pragma unroll
            for (int u = 0; u < 4; u++) {
                int jj = tid + u * 256;
                int row = jj >> 4, c8 = (jj & 15) * 8;
                const __nv_bfloat16* gp = gb + (size_t)(kt * 64 + row) * KVD + c8;
                uint32_t sm = sb0 + (uint32_t)((sec * 64 + row) * VP + c8) * 2;
                CP16(sm, gp);
            }
        }
    };

    // stage Q into buffer 2; start tiles t0, t0+1 into buffers 0,1
    #pragma unroll
    for (int u = 0; u < 8; u++) {
        int i = tid + u * 256;
        int row = i >> 4, c8 = (i & 15) * 8;
        *(uint4*)&SB[2 * BUF_ELE + row * VP + c8] = *(const uint4*)(qhig + (size_t)row * ED + c8);
        *(uint4*)&SB[2 * BUF_ELE + (128 + row) * VP + c8] = *(const uint4*)(qlog + (size_t)row * ED + c8);
    }
    issue(t0, 0);
    CPCOMMIT();
    issue(t0 + 1, 1);
    CPCOMMIT();
    __syncthreads();

    uint32_t qh[8][4], ql[8][4];
    {
        int ar = lid & 15, ak8 = (lid >> 4) * 8;
        #pragma unroll
        for (int j = 0; j < 8; j++) {
            uint32_t adh = sbase + (uint32_t)(2 * BUF_ELE + (wid * 16 + ar) * VP + j * 16 + ak8) * 2;
            LDSM4(qh[j][0], qh[j][1], qh[j][2], qh[j][3], adh);
            uint32_t adl = sbase + (uint32_t)(2 * BUF_ELE + (128 + wid * 16 + ar) * VP + j * 16 + ak8) * 2;
            LDSM4(ql[j][0], ql[j][1], ql[j][2], ql[j][3], adl);
        }
    }
    __syncthreads();   // buffer 2 free for tile t0+2 (issued at iter 0)

    float m_[2] = {-1e30f, -1e30f}, l_[2] = {0.f, 0.f};
    float o[16][4];
    #pragma unroll
    for (int i = 0; i < 16; i++)
        #pragma unroll
        for (int q = 0; q < 4; q++) o[i][q] = 0.f;

    int b_n  = (lid & 7) + ((lid >> 4) & 1) * 8;
    int b_k8 = ((lid >> 3) & 1) * 8;
    int v_r  = lid & 15, v_n8 = (lid >> 4) * 8;

    int cur = 0, nx2 = 2;
    #pragma unroll 1
    for (int kt = 0; kt < TPS; kt++) {
        if (kt < TPS - 1) { CPWAIT1(); } else { CPWAIT0(); }
        __syncthreads();
        if (kt + 2 < TPS) { issue(t0 + kt + 2, nx2); CPCOMMIT(); }

        uint32_t kb = (uint32_t)(cur * BUF_ELE);
        uint32_t sKH = kb, sKL = kb + 64 * VP, sVH = kb + 128 * VP, sVL = kb + 192 * VP;

        float S[8][4];
        #pragma unroll
        for (int nt = 0; nt < 8; nt++)
            #pragma unroll
            for (int q = 0; q < 4; q++) S[nt][q] = 0.f;
        #pragma unroll
        for (int j = 0; j < 8; j++) {
            #pragma unroll
            for (int g = 0; g < 4; g++) {
                uint32_t bh0, bh1, bh2, bh3, bl0, bl1, bl2, bl3;
                uint32_t adh = sbase + (uint32_t)(sKH + (g * 16 + b_n) * VP + j * 16 + b_k8) * 2;
                LDSM4(bh0, bh1, bh2, bh3, adh);
                uint32_t adl = sbase + (uint32_t)(sKL + (g * 16 + b_n) * VP + j * 16 + b_k8) * 2;
                LDSM4(bl0, bl1, bl2, bl3, adl);
                MMA16816(S[2*g],   qh[j][0], qh[j][1], qh[j][2], qh[j][3], bh0, bh1);
                MMA16816(S[2*g],   qh[j][0], qh[j][1], qh[j][2], qh[j][3], bl0, bl1);
                MMA16816(S[2*g],   ql[j][0], ql[j][1], ql[j][2], ql[j][3], bh0, bh1);
                MMA16816(S[2*g+1], qh[j][0], qh[j][1], qh[j][2], qh[j][3], bh2, bh3);
                MMA16816(S[2*g+1], qh[j][0], qh[j][1], qh[j][2], qh[j][3], bl2, bl3);
                MMA16816(S[2*g+1], ql[j][0], ql[j][1], ql[j][2], ql[j][3], bh2, bh3);
            }
        }

        #pragma unroll
        for (int rr = 0; rr < 2; rr++) {
            int c0 = rr * 2;
            float mx = -1e30f;
            #pragma unroll
            for (int nt = 0; nt < 8; nt++)
                mx = fmaxf(mx, fmaxf(S[nt][c0], S[nt][c0 + 1]));
            mx = fmaxf(mx, __shfl_xor_sync(0xffffffffu, mx, 1));
            mx = fmaxf(mx, __shfl_xor_sync(0xffffffffu, mx, 2));
            if (mx > m_[rr]) {
                float corr = exp2f(m_[rr] - mx);
                m_[rr] = mx;
                l_[rr] *= corr;
                #pragma unroll
                for (int nt = 0; nt < 16; nt++) {
                    o[nt][c0] *= corr; o[nt][c0 + 1] *= corr;
                }
            }
            float mn = m_[rr];
            float sum = 0.f;
            #pragma unroll
            for (int nt = 0; nt < 8; nt++) {
                float p0 = exp2f(S[nt][c0] - mn);
                float p1 = exp2f(S[nt][c0 + 1] - mn);
                S[nt][c0] = p0; S[nt][c0 + 1] = p1;
                sum += p0 + p1;
            }
            sum += __shfl_xor_sync(0xffffffffu, sum, 1);
            sum += __shfl_xor_sync(0xffffffffu, sum, 2);
            l_[rr] += sum;
        }

        uint32_t ph[4][4], pl[4][4];
        #pragma unroll
        for (int jp = 0; jp < 4; jp++) {
            #pragma unroll
            for (int q = 0; q < 4; q++) {
                int nt = 2 * jp + (q >> 1);
                int c0 = (q & 1) * 2;
                float x = S[nt][c0], y = S[nt][c0 + 1];
                __nv_bfloat16 hx = __float2bfloat16_rn(x);
                __nv_bfloat16 hy = __float2bfloat16_rn(y);
                ph[jp][q] = (unsigned)__bfloat16_as_ushort(hx) |
                            ((unsigned)__bfloat16_as_ushort(hy) << 16);
                pl[jp][q] = pack_bf2(x - __bfloat162float(hx), y - __bfloat162float(hy));
            }
        }

        #pragma unroll
        for (int jp = 0; jp < 4; jp++) {
            #pragma unroll
            for (int g = 0; g < 8; g++) {
                uint32_t vh0, vh1, vh2, vh3, vl0, vl1, vl2, vl3;
                uint32_t adh = sbase + (uint32_t)(sVH + (jp * 16 + v_r) * VP + g * 16 + v_n8) * 2;
                LDSM4T(vh0, vh1, vh2, vh3, adh);
                uint32_t adl = sbase + (uint32_t)(sVL + (jp * 16 + v_r) * VP + g * 16 + v_n8) * 2;
                LDSM4T(vl0, vl1, vl2, vl3, adl);
                MMA16816(o[2*g],   ph[jp][0], ph[jp][1], ph[jp][2], ph[jp][3], vh0, vh1);
                MMA16816(o[2*g],   ph[jp][0], ph[jp][1], ph[jp][2], ph[jp][3], vl0, vl1);
                MMA16816(o[2*g],   pl[jp][0], pl[jp][1], pl[jp][2], pl[jp][3], vh0, vh1);
                MMA16816(o[2*g+1], ph[jp][0], ph[jp][1], ph[jp][2], ph[jp][3], vh2, vh3);
                MMA16816(o[2*g+1], ph[jp][0], ph[jp][1], ph[jp][2], ph[jp][3], vl2, vl3);
                MMA16816(o[2*g+1], pl[jp][0], pl[jp][1], pl[jp][2], pl[jp][3], vh2, vh3);
            }
        }

        cur = (cur == 2) ? 0 : cur + 1;
        nx2 = (nx2 == 2) ? 0 : nx2 + 1;
    }

    // ---- epilogue: write unnormalized partials (o, m, l) ----
    float* po = &g_po[split][bh][qt][0];
    #pragma unroll
    for (int rr = 0; rr < 2; rr++) {
        int srow = wid * 16 + (lid >> 2) + rr * 8;
        if ((lid & 3) == 0) {
            g_pm[split][bh][qt][srow] = m_[rr];
            g_pl[split][bh][qt][srow] = l_[rr];
        }
        float* pr = po + (size_t)srow * 128 + (lid & 3) * 2;
        #pragma unroll
        for (int nt = 0; nt < 16; nt++) {
            *(float2*)&pr[nt * 8] = make_float2(o[nt][rr * 2], o[nt][rr * 2 + 1]);
        }
    }
}

// ---------------- split-KV combine: warp per row (exact flash merge) ----------------
__global__ void __launch_bounds__(256) attn_combine() {
    int lane = threadIdx.x & 31;
    int gw = blockIdx.x * 8 + (threadIdx.x >> 5);   // 0 .. 32767
    int row = gw & 127, qt = (gw >> 7) & 15, bh = gw >> 11;
    int b = bh >> 3, h = bh & 7;
    float m0 = g_pm[0][bh][qt][row], m1 = g_pm[1][bh][qt][row];
    float m2 = g_pm[2][bh][qt][row], m3 = g_pm[3][bh][qt][row];
    float M = fmaxf(fmaxf(m0, m1), fmaxf(m2, m3));
    float w0 = exp2f(m0 - M), w1 = exp2f(m1 - M);
    float w2 = exp2f(m2 - M), w3 = exp2f(m3 - M);
    float L = w0 * g_pl[0][bh][qt][row] + w1 * g_pl[1][bh][qt][row]
            + w2 * g_pl[2][bh][qt][row] + w3 * g_pl[3][bh][qt][row];
    float inv = 1.f / L;
    size_t off = (size_t)row * 128 + lane * 4;
    float4 o0 = *(const float4*)&g_po[0][bh][qt][off];
    float4 o1 = *(const float4*)&g_po[1][bh][qt][off];
    float4 o2 = *(const float4*)&g_po[2][bh][qt][off];
    float4 o3 = *(const float4*)&g_po[3][bh][qt][off];
    float4 r;
    r.x = (w0 * o0.x + w1 * o1.x + w2 * o2.x + w3 * o3.x) * inv;
    r.y = (w0 * o0.y + w1 * o1.y + w2 * o2.y + w3 * o3.y) * inv;
    r.z = (w0 * o0.z + w1 * o1.z + w2 * o2.z + w3 * o3.z) * inv;
    r.w = (w0 * o0.w + w1 * o1.w + w2 * o2.w + w3 * o3.w) * inv;
    float* xo = g_x + ((size_t)b * SEQ + qt * 128 + row) * ED + h * HD + lane * 4;
    *(float4*)xo = r;
}

// ---------------- launch ----------------
extern "C" void kernel_launch(void* const* d_in, const int* in_sizes, int n_in,
                              void* d_out, int out_size) {
    const float* query = (const float*)d_in[0];
    const float* key   = (const float*)d_in[1];
    const float* value = (const float*)d_in[2];
    const float* q_w   = (const float*)d_in[3];
    const float* q_b   = (const float*)d_in[4];
    const float* k_w   = (const float*)d_in[5];
    const float* k_b   = (const float*)d_in[6];
    const float* v_w   = (const float*)d_in[7];
    const float* v_b   = (const float*)d_in[8];
    const float* ln_g  = (const float*)d_in[9];
    const float* ln_b  = (const float*)d_in[10];
    const float* out_w = (const float*)d_in[11];
    const float* out_b = (const float*)d_in[12];

    cudaFuncSetAttribute(attn_mma, cudaFuncAttributeMaxDynamicSharedMemorySize, ATTN_SMEM);
    cudaFuncSetAttribute(gemm_qkv, cudaFuncAttributeMaxDynamicSharedMemorySize, GEMM_SMEM);
    cudaFuncSetAttribute(gemm_out, cudaFuncAttributeMaxDynamicSharedMemorySize, GEMM_SMEM);

    // weight prep (1 launch) + final reduce
    prep_w<<<dim3(256, 4), 256>>>((const float4*)q_w, (const float4*)k_w,
                                  (const float4*)v_w, (const float4*)out_w);
    absmean_final<<<4, 256>>>();

    // activation quants (warp-per-token), then projections (1 launch)
    quant_rms<<<dim3(NTOK / 8, 3), 256>>>(query, key, value);
    gemm_qkv<<<384, 256, GEMM_SMEM>>>(q_b, k_b, v_b);

    // attention: split-KV x4 (1024 CTAs) + exact combine
    attn_mma<<<dim3(SEQ / 128, 16, NSPLIT), 256, ATTN_SMEM>>>();
    attn_combine<<<4096, 256>>>();

    // layernorm + final bitlinear
    ln_quant<<<NTOK / 8, 256>>>(ln_g, ln_b);
    gemm_out<<<256, 256, GEMM_SMEM>>>(out_b, (float*)d_out);
}

// round 17
// speedup vs baseline: 1.0375x; 1.0153x over previous
#include <cuda_runtime.h>
#include <cuda_bf16.h>
#include <math.h>
#include <stdint.h>

#define SEQ   2048
#define NTOK  4096
#define ED    1024
#define KVD   256
#define HD    128
#define QSC   0.08838834764831845f   // 1/sqrt(128)
#define LOG2E 1.44269504088896340736f
#define NSPLIT 4
#define TPS    8                      // KV tiles per split (32/NSPLIT)

// ---------------- device scratch (no allocations allowed) ----------------
__device__ float g_alpha[4];
__device__ float g_part[4][256];
__device__ __nv_bfloat16 g_wq[ED*ED];
__device__ __nv_bfloat16 g_wk[KVD*ED];
__device__ __nv_bfloat16 g_wv[KVD*ED];
__device__ __nv_bfloat16 g_wo[ED*ED];
__device__ __nv_bfloat16 g_actbf[3*NTOK*ED];   // slot 0:q(=out later) 1:k 2:v
__device__ float g_fact[3*NTOK];
__device__ __nv_bfloat16 g_qhi[NTOK*ED];
__device__ __nv_bfloat16 g_qlo[NTOK*ED];
__device__ __nv_bfloat16 g_khi[NTOK*KVD];
__device__ __nv_bfloat16 g_klo[NTOK*KVD];
__device__ __nv_bfloat16 g_vhi[NTOK*KVD];
__device__ __nv_bfloat16 g_vlo[NTOK*KVD];
// split-KV attention partials: [split][bh][qt][...]
__device__ float g_po[NSPLIT][16][16][128*128];
__device__ float g_pm[NSPLIT][16][16][128];
__device__ float g_pl[NSPLIT][16][16][128];

__device__ __forceinline__ __nv_bfloat16* sel_w(int m) {
    return m == 0 ? g_wq : m == 1 ? g_wk : m == 2 ? g_wv : g_wo;
}

__device__ __forceinline__ uint32_t smem_u32(const void* p) {
    uint32_t a;
    asm("{ .reg .u64 t; cvta.to.shared.u64 t, %1; cvt.u32.u64 %0, t; }" : "=r"(a) : "l"(p));
    return a;
}
__device__ __forceinline__ unsigned pack_bf2(float a, float b) {
    return (unsigned)__bfloat16_as_ushort(__float2bfloat16_rn(a)) |
           ((unsigned)__bfloat16_as_ushort(__float2bfloat16_rn(b)) << 16);
}

#define LDSM4(R0,R1,R2,R3,ADDR) \
    asm volatile("ldmatrix.sync.aligned.m8n8.x4.shared.b16 {%0,%1,%2,%3}, [%4];" \
        : "=r"(R0), "=r"(R1), "=r"(R2), "=r"(R3) : "r"(ADDR))
#define LDSM4T(R0,R1,R2,R3,ADDR) \
    asm volatile("ldmatrix.sync.aligned.m8n8.x4.trans.shared.b16 {%0,%1,%2,%3}, [%4];" \
        : "=r"(R0), "=r"(R1), "=r"(R2), "=r"(R3) : "r"(ADDR))
#define MMA16816(C, A0,A1,A2,A3, B0,B1) \
    asm volatile("mma.sync.aligned.m16n8k16.row.col.f32.bf16.bf16.f32 " \
        "{%0,%1,%2,%3}, {%4,%5,%6,%7}, {%8,%9}, {%0,%1,%2,%3};" \
        : "+f"((C)[0]), "+f"((C)[1]), "+f"((C)[2]), "+f"((C)[3]) \
        : "r"(A0), "r"(A1), "r"(A2), "r"(A3), "r"(B0), "r"(B1))
#define CP16(SM_, GP_) \
    asm volatile("cp.async.cg.shared.global [%0], [%1], 16;" :: "r"(SM_), "l"(GP_))
#define CPCOMMIT() asm volatile("cp.async.commit_group;" ::: "memory")
#define CPWAIT1()  asm volatile("cp.async.wait_group 1;" ::: "memory")
#define CPWAIT0()  asm volatile("cp.async.wait_group 0;" ::: "memory")

// ---------------- fused weight prep (one launch, grid.y = mid) ----------------
__global__ void prep_w(const float4* __restrict__ w0, const float4* __restrict__ w1,
                       const float4* __restrict__ w2, const float4* __restrict__ w3) {
    __shared__ float sh[256];
    int mid = blockIdx.y;
    const float4* w = mid == 0 ? w0 : mid == 1 ? w1 : mid == 2 ? w2 : w3;
    int n4 = (mid == 1 || mid == 2) ? (KVD * ED / 4) : (ED * ED / 4);
    float s = 0.f;
    uint2* dst = (uint2*)sel_w(mid);
    for (int i = blockIdx.x * 256 + threadIdx.x; i < n4; i += 256 * 256) {
        float4 v = w[i];
        s += fabsf(v.x) + fabsf(v.y) + fabsf(v.z) + fabsf(v.w);
        uint2 c;
        c.x = pack_bf2((float)((v.x > 0.f) - (v.x < 0.f)), (float)((v.y > 0.f) - (v.y < 0.f)));
        c.y = pack_bf2((float)((v.z > 0.f) - (v.z < 0.f)), (float)((v.w > 0.f) - (v.w < 0.f)));
        dst[i] = c;
    }
    sh[threadIdx.x] = s;
    __syncthreads();
    for (int o = 128; o > 0; o >>= 1) {
        if (threadIdx.x < o) sh[threadIdx.x] += sh[threadIdx.x + o];
        __syncthreads();
    }
    if (threadIdx.x == 0) g_part[mid][blockIdx.x] = sh[0];
}

__global__ void absmean_final() {
    int m = blockIdx.x;
    __shared__ float sh[256];
    sh[threadIdx.x] = g_part[m][threadIdx.x];
    __syncthreads();
    for (int o = 128; o > 0; o >>= 1) {
        if (threadIdx.x < o) sh[threadIdx.x] += sh[threadIdx.x + o];
        __syncthreads();
    }
    if (threadIdx.x == 0) {
        float n = (m == 1 || m == 2) ? (float)(KVD * ED) : (float)(ED * ED);
        g_alpha[m] = sh[0] / n;
    }
}

// ---------------- RMSNorm + activation quant: warp-per-token ----------------
__global__ void __launch_bounds__(256) quant_rms(const float* __restrict__ q,
                                                 const float* __restrict__ k,
                                                 const float* __restrict__ vv) {
    int slot = blockIdx.y;
    const float* x = slot == 0 ? q : slot == 1 ? k : vv;
    int lane = threadIdx.x & 31;
    int tok = blockIdx.x * 8 + (threadIdx.x >> 5);
    const float4* xr = (const float4*)(x + (size_t)tok * ED);
    float4 v[8];
    #pragma unroll
    for (int i = 0; i < 8; i++) v[i] = xr[lane + i * 32];
    float ss = 0.f, am = 0.f;
    #pragma unroll
    for (int i = 0; i < 8; i++) {
        ss += v[i].x * v[i].x + v[i].y * v[i].y + v[i].z * v[i].z + v[i].w * v[i].w;
        am = fmaxf(am, fmaxf(fmaxf(fabsf(v[i].x), fabsf(v[i].y)),
                             fmaxf(fabsf(v[i].z), fabsf(v[i].w))));
    }
    #pragma unroll
    for (int o = 16; o; o >>= 1) {
        ss += __shfl_xor_sync(0xffffffffu, ss, o);
        am = fmaxf(am, __shfl_xor_sync(0xffffffffu, am, o));
    }
    float r = 1.f / (sqrtf(ss * (1.f / ED) + 1e-6f) * 32.f);
    float scale = 127.f / fmaxf(am * r, 1e-5f);
    if (lane == 0) g_fact[slot * NTOK + tok] = 1.f / scale;
    float f = r * scale;
    uint2* dst = (uint2*)g_actbf + (size_t)slot * NTOK * (ED / 4) + (size_t)tok * (ED / 4);
    #pragma unroll
    for (int i = 0; i < 8; i++) {
        float qx = fminf(fmaxf(rintf(v[i].x * f), -128.f), 127.f);
        float qy = fminf(fmaxf(rintf(v[i].y * f), -128.f), 127.f);
        float qz = fminf(fmaxf(rintf(v[i].z * f), -128.f), 127.f);
        float qw = fminf(fmaxf(rintf(v[i].w * f), -128.f), 127.f);
        uint2 c; c.x = pack_bf2(qx, qy); c.y = pack_bf2(qz, qw);
        dst[lane + i * 32] = c;
    }
}

// ------ fused split-KV combine + LayerNorm + RMSNorm + quant: warp-per-token ------
// For token tok, unroll index i maps exactly to head i; all heads share the
// same intra-head offset row*128 + lane*4. Merge partials with the identical
// fp32 flash-merge arithmetic the standalone combine kernel used.
__global__ void __launch_bounds__(256) ln_quant(const float* __restrict__ g,
                                                const float* __restrict__ bb) {
    int lane = threadIdx.x & 31;
    int tok = blockIdx.x * 8 + (threadIdx.x >> 5);
    int b = tok >> 11;             // 2048 tokens per batch
    int srow = tok & 2047;
    int qt = srow >> 7, row = srow & 127;
    size_t off = (size_t)row * 128 + lane * 4;
    const float4* gg = (const float4*)g;
    const float4* bv = (const float4*)bb;
    float4 v[8];
    #pragma unroll
    for (int i = 0; i < 8; i++) {
        int bh = b * 8 + i;
        float m0 = g_pm[0][bh][qt][row], m1 = g_pm[1][bh][qt][row];
        float m2 = g_pm[2][bh][qt][row], m3 = g_pm[3][bh][qt][row];
        float M = fmaxf(fmaxf(m0, m1), fmaxf(m2, m3));
        float w0 = exp2f(m0 - M), w1 = exp2f(m1 - M);
        float w2 = exp2f(m2 - M), w3 = exp2f(m3 - M);
        float L = w0 * g_pl[0][bh][qt][row] + w1 * g_pl[1][bh][qt][row]
                + w2 * g_pl[2][bh][qt][row] + w3 * g_pl[3][bh][qt][row];
        float inv = 1.f / L;
        float4 o0 = *(const float4*)&g_po[0][bh][qt][off];
        float4 o1 = *(const float4*)&g_po[1][bh][qt][off];
        float4 o2 = *(const float4*)&g_po[2][bh][qt][off];
        float4 o3 = *(const float4*)&g_po[3][bh][qt][off];
        v[i].x = (w0 * o0.x + w1 * o1.x + w2 * o2.x + w3 * o3.x) * inv;
        v[i].y = (w0 * o0.y + w1 * o1.y + w2 * o2.y + w3 * o3.y) * inv;
        v[i].z = (w0 * o0.z + w1 * o1.z + w2 * o2.z + w3 * o3.z) * inv;
        v[i].w = (w0 * o0.w + w1 * o1.w + w2 * o2.w + w3 * o3.w) * inv;
    }
    float s1 = 0.f, s2 = 0.f;
    #pragma unroll
    for (int i = 0; i < 8; i++) {
        s1 += v[i].x + v[i].y + v[i].z + v[i].w;
        s2 += v[i].x * v[i].x + v[i].y * v[i].y + v[i].z * v[i].z + v[i].w * v[i].w;
    }
    #pragma unroll
    for (int o = 16; o; o >>= 1) {
        s1 += __shfl_xor_sync(0xffffffffu, s1, o);
        s2 += __shfl_xor_sync(0xffffffffu, s2, o);
    }
    float mu = s1 * (1.f / ED);
    float var = fmaxf(s2 * (1.f / ED) - mu * mu, 0.f);
    float inv = rsqrtf(var + 1e-5f);
    float ss = 0.f, am = 0.f;
    #pragma unroll
    for (int i = 0; i < 8; i++) {
        float4 gi = gg[lane + i * 32], bi = bv[lane + i * 32];
        float lx = (v[i].x - mu) * inv * gi.x + bi.x;
        float ly = (v[i].y - mu) * inv * gi.y + bi.y;
        float lz = (v[i].z - mu) * inv * gi.z + bi.z;
        float lw = (v[i].w - mu) * inv * gi.w + bi.w;
        ss += lx * lx + ly * ly + lz * lz + lw * lw;
        am = fmaxf(am, fmaxf(fmaxf(fabsf(lx), fabsf(ly)), fmaxf(fabsf(lz), fabsf(lw))));
    }
    #pragma unroll
    for (int o = 16; o; o >>= 1) {
        ss += __shfl_xor_sync(0xffffffffu, ss, o);
        am = fmaxf(am, __shfl_xor_sync(0xffffffffu, am, o));
    }
    float r = 1.f / (sqrtf(ss * (1.f / ED) + 1e-6f) * 32.f);
    float scale = 127.f / fmaxf(am * r, 1e-5f);
    if (lane == 0) g_fact[tok] = 1.f / scale;
    float f = r * scale;
    uint2* dst = (uint2*)g_actbf + (size_t)tok * (ED / 4);
    #pragma unroll
    for (int i = 0; i < 8; i++) {
        float4 gi = gg[lane + i * 32], bi = bv[lane + i * 32];
        float lx = (v[i].x - mu) * inv * gi.x + bi.x;
        float ly = (v[i].y - mu) * inv * gi.y + bi.y;
        float lz = (v[i].z - mu) * inv * gi.z + bi.z;
        float lw = (v[i].w - mu) * inv * gi.w + bi.w;
        float qx = fminf(fmaxf(rintf(lx * f), -128.f), 127.f);
        float qy = fminf(fmaxf(rintf(ly * f), -128.f), 127.f);
        float qz = fminf(fmaxf(rintf(lz * f), -128.f), 127.f);
        float qw = fminf(fmaxf(rintf(lw * f), -128.f), 127.f);
        uint2 c; c.x = pack_bf2(qx, qy); c.y = pack_bf2(qz, qw);
        dst[lane + i * 32] = c;
    }
}

// ---------------- exact bf16 HMMA GEMM body (R11: LDG+STS double buffer) ----------------
#define GP   72
#define BUFB (128 * GP * 2)
#define GEMM_SMEM (4 * BUFB)

__device__ __forceinline__ void gemm_body(int mid, const float* __restrict__ bias,
                                          int Nout, float* __restrict__ Cext,
                                          int bm, int bn, char* SM) {
    uint32_t sbase = smem_u32(SM);
    int aslot = (mid == 3) ? 0 : mid;
    const __nv_bfloat16* A = g_actbf + (size_t)aslot * NTOK * ED;
    const __nv_bfloat16* B = sel_w(mid);
    int tid = threadIdx.x, wid = tid >> 5, lid = tid & 31;
    int wm = wid & 3, wn = wid >> 2;
    int m0 = bm * 128, n0 = bn * 128;

    auto Aoff = [&](int b) { return (uint32_t)(b * 2 * BUFB); };
    auto Boff = [&](int b) { return (uint32_t)(b * 2 * BUFB + BUFB); };

    int lrow = tid >> 3;
    int lc8  = (tid & 7) * 8;

    {
        const __nv_bfloat16* Ag = A + (size_t)(m0) * ED;
        const __nv_bfloat16* Bg = B + (size_t)(n0) * ED;
        #pragma unroll
        for (int u = 0; u < 4; u++) {
            int row = lrow + u * 32;
            *(uint4*)(SM + Aoff(0) + (row * GP + lc8) * 2) =
                *(const uint4*)(Ag + (size_t)row * ED + lc8);
            *(uint4*)(SM + Boff(0) + (row * GP + lc8) * 2) =
                *(const uint4*)(Bg + (size_t)row * ED + lc8);
        }
    }
    __syncthreads();

    float acc[2][8][4];
    #pragma unroll
    for (int i = 0; i < 2; i++)
        #pragma unroll
        for (int j = 0; j < 8; j++)
            #pragma unroll
            for (int q = 0; q < 4; q++) acc[i][j][q] = 0.f;

    int a_r = lid & 15, a_k8 = (lid >> 4) * 8;
    int b_n = (lid & 7) + ((lid >> 4) & 1) * 8;
    int b_k8 = ((lid >> 3) & 1) * 8;

    #pragma unroll 1
    for (int kt = 0; kt < 16; kt++) {
        int cur = kt & 1;
        uint4 pa[4], pb[4];
        if (kt + 1 < 16) {
            const __nv_bfloat16* Ag = A + (size_t)m0 * ED + (kt + 1) * 64;
            const __nv_bfloat16* Bg = B + (size_t)n0 * ED + (kt + 1) * 64;
            #pragma unroll
            for (int u = 0; u < 4; u++) {
                int row = lrow + u * 32;
                pa[u] = *(const uint4*)(Ag + (size_t)row * ED + lc8);
                pb[u] = *(const uint4*)(Bg + (size_t)row * ED + lc8);
            }
        }
        uint32_t sA = sbase + Aoff(cur), sB = sbase + Boff(cur);
        #pragma unroll
        for (int ks = 0; ks < 4; ks++) {
            uint32_t a[2][4];
            #pragma unroll
            for (int mt = 0; mt < 2; mt++) {
                uint32_t ad = sA + ((wm * 32 + mt * 16 + a_r) * GP + ks * 16 + a_k8) * 2;
                LDSM4(a[mt][0], a[mt][1], a[mt][2], a[mt][3], ad);
            }
            #pragma unroll
            for (int np = 0; np < 4; np++) {
                uint32_t b0, b1, b2, b3;
                uint32_t bd = sB + ((wn * 64 + np * 16 + b_n) * GP + ks * 16 + b_k8) * 2;
                LDSM4(b0, b1, b2, b3, bd);
                MMA16816(acc[0][np * 2 + 0], a[0][0], a[0][1], a[0][2], a[0][3], b0, b1);
                MMA16816(acc[0][np * 2 + 1], a[0][0], a[0][1], a[0][2], a[0][3], b2, b3);
                MMA16816(acc[1][np * 2 + 0], a[1][0], a[1][1], a[1][2], a[1][3], b0, b1);
                MMA16816(acc[1][np * 2 + 1], a[1][0], a[1][1], a[1][2], a[1][3], b2, b3);
            }
        }
        if (kt + 1 < 16) {
            int nxt = cur ^ 1;
            #pragma unroll
            for (int u = 0; u < 4; u++) {
                int row = lrow + u * 32;
                *(uint4*)(SM + Aoff(nxt) + (row * GP + lc8) * 2) = pa[u];
                *(uint4*)(SM + Boff(nxt) + (row * GP + lc8) * 2) = pb[u];
            }
            __syncthreads();
        }
    }

    float alpha = g_alpha[mid];
    float qmul = (mid == 0) ? (QSC * LOG2E) : 1.f;
    __nv_bfloat16* Hp = (mid == 0) ? g_qhi : (mid == 1) ? g_khi : g_vhi;
    __nv_bfloat16* Lp = (mid == 0) ? g_qlo : (mid == 1) ? g_klo : g_vlo;
    int trow = lid >> 2, tcol = (lid & 3) * 2;
    #pragma unroll
    for (int mt = 0; mt < 2; mt++) {
        int r0 = m0 + wm * 32 + mt * 16 + trow;
        float sf0 = alpha * qmul * g_fact[aslot * NTOK + r0];
        float sf1 = alpha * qmul * g_fact[aslot * NTOK + r0 + 8];
        #pragma unroll
        for (int nt = 0; nt < 8; nt++) {
            int cc = n0 + wn * 64 + nt * 8 + tcol;
            float bx = bias[cc] * qmul, by = bias[cc + 1] * qmul;
            float c00 = acc[mt][nt][0] * sf0 + bx, c01 = acc[mt][nt][1] * sf0 + by;
            float c10 = acc[mt][nt][2] * sf1 + bx, c11 = acc[mt][nt][3] * sf1 + by;
            if (mid == 3) {
                *(float2*)&Cext[(size_t)r0 * Nout + cc] = make_float2(c00, c01);
                *(float2*)&Cext[(size_t)(r0 + 8) * Nout + cc] = make_float2(c10, c11);
            } else {
                __nv_bfloat16 h00 = __float2bfloat16_rn(c00), h01 = __float2bfloat16_rn(c01);
                __nv_bfloat16 h10 = __float2bfloat16_rn(c10), h11 = __float2bfloat16_rn(c11);
                *(uint*)&Hp[(size_t)r0 * Nout + cc] =
                    (unsigned)__bfloat16_as_ushort(h00) | ((unsigned)__bfloat16_as_ushort(h01) << 16);
                *(uint*)&Hp[(size_t)(r0 + 8) * Nout + cc] =
                    (unsigned)__bfloat16_as_ushort(h10) | ((unsigned)__bfloat16_as_ushort(h11) << 16);
                *(uint*)&Lp[(size_t)r0 * Nout + cc] =
                    pack_bf2(c00 - __bfloat162float(h00), c01 - __bfloat162float(h01));
                *(uint*)&Lp[(size_t)(r0 + 8) * Nout + cc] =
                    pack_bf2(c10 - __bfloat162float(h10), c11 - __bfloat162float(h11));
            }
        }
    }
}

__global__ void __launch_bounds__(256) gemm_qkv(const float* __restrict__ qb,
                                                const float* __restrict__ kb,
                                                const float* __restrict__ vb) {
    extern __shared__ char SM[];
    int item = blockIdx.x;
    int mid, bm, bn, Nout;
    const float* bias;
    if (item < 256)      { mid = 0; bias = qb; Nout = ED;  bm = item >> 3;        bn = item & 7; }
    else if (item < 320) { mid = 1; bias = kb; Nout = KVD; bm = (item - 256) >> 1; bn = (item - 256) & 1; }
    else                 { mid = 2; bias = vb; Nout = KVD; bm = (item - 320) >> 1; bn = (item - 320) & 1; }
    gemm_body(mid, bias, Nout, nullptr, bm, bn, SM);
}

__global__ void __launch_bounds__(256) gemm_out(const float* __restrict__ bias,
                                                float* __restrict__ Cext) {
    extern __shared__ char SM[];
    gemm_body(3, bias, ED, Cext, blockIdx.x >> 3, blockIdx.x & 7, SM);
}

// ---------------- HMMA flash attention: split-KV x4, 3-stage cp.async ----------------
#define VP 136
#define BUF_ELE (256 * VP)
#define ATTN_SMEM (3 * BUF_ELE * 2)        // 208896 B

__global__ void __launch_bounds__(256, 1) attn_mma() {
    extern __shared__ __nv_bfloat16 SB[];
    uint32_t sbase = smem_u32(SB);
    int tid = threadIdx.x, wid = tid >> 5, lid = tid & 31;
    int qt = blockIdx.x, bh = blockIdx.y, split = blockIdx.z;
    int b = bh >> 3, h = bh & 7, kvh = h >> 2;
    int t0 = split * TPS;
    const __nv_bfloat16* qhig = g_qhi + ((size_t)b * SEQ + qt * 128) * ED + h * HD;
    const __nv_bfloat16* qlog = g_qlo + ((size_t)b * SEQ + qt * 128) * ED + h * HD;
    const __nv_bfloat16* khig = g_khi + (size_t)b * SEQ * KVD + kvh * HD;
    const __nv_bfloat16* klog = g_klo + (size_t)b * SEQ * KVD + kvh * HD;
    const __nv_bfloat16* vhig = g_vhi + (size_t)b * SEQ * KVD + kvh * HD;
    const __nv_bfloat16* vlog = g_vlo + (size_t)b * SEQ * KVD + kvh * HD;

    auto issue = [&](int kt, int buf) {
        uint32_t sb0 = sbase + (uint32_t)(buf * BUF_ELE) * 2;
        #pragma unroll
        for (int sec = 0; sec < 4; sec++) {
            const __nv_bfloat16* gb = (sec == 0) ? khig : (sec == 1) ? klog
                                     : (sec == 2) ? vhig : vlog;
            #pragma unroll
            for (int u = 0; u < 4; u++) {
                int jj = tid + u * 256;
                int row = jj >> 4, c8 = (jj & 15) * 8;
                const __nv_bfloat16* gp = gb + (size_t)(kt * 64 + row) * KVD + c8;
                uint32_t sm = sb0 + (uint32_t)((sec * 64 + row) * VP + c8) * 2;
                CP16(sm, gp);
            }
        }
    };

    // stage Q into buffer 2; start tiles t0, t0+1 into buffers 0,1
    #pragma unroll
    for (int u = 0; u < 8; u++) {
        int i = tid + u * 256;
        int row = i >> 4, c8 = (i & 15) * 8;
        *(uint4*)&SB[2 * BUF_ELE + row * VP + c8] = *(const uint4*)(qhig + (size_t)row * ED + c8);
        *(uint4*)&SB[2 * BUF_ELE + (128 + row) * VP + c8] = *(const uint4*)(qlog + (size_t)row * ED + c8);
    }
    issue(t0, 0);
    CPCOMMIT();
    issue(t0 + 1, 1);
    CPCOMMIT();
    __syncthreads();

    uint32_t qh[8][4], ql[8][4];
    {
        int ar = lid & 15, ak8 = (lid >> 4) * 8;
        #pragma unroll
        for (int j = 0; j < 8; j++) {
            uint32_t adh = sbase + (uint32_t)(2 * BUF_ELE + (wid * 16 + ar) * VP + j * 16 + ak8) * 2;
            LDSM4(qh[j][0], qh[j][1], qh[j][2], qh[j][3], adh);
            uint32_t adl = sbase + (uint32_t)(2 * BUF_ELE + (128 + wid * 16 + ar) * VP + j * 16 + ak8) * 2;
            LDSM4(ql[j][0], ql[j][1], ql[j][2], ql[j][3], adl);
        }
    }
    __syncthreads();   // buffer 2 free for tile t0+2 (issued at iter 0)

    float m_[2] = {-1e30f, -1e30f}, l_[2] = {0.f, 0.f};
    float o[16][4];
    #pragma unroll
    for (int i = 0; i < 16; i++)
        #pragma unroll
        for (int q = 0; q < 4; q++) o[i][q] = 0.f;

    int b_n  = (lid & 7) + ((lid >> 4) & 1) * 8;
    int b_k8 = ((lid >> 3) & 1) * 8;
    int v_r  = lid & 15, v_n8 = (lid >> 4) * 8;

    int cur = 0, nx2 = 2;
    #pragma unroll 1
    for (int kt = 0; kt < TPS; kt++) {
        if (kt < TPS - 1) { CPWAIT1(); } else { CPWAIT0(); }
        __syncthreads();
        if (kt + 2 < TPS) { issue(t0 + kt + 2, nx2); CPCOMMIT(); }

        uint32_t kb = (uint32_t)(cur * BUF_ELE);
        uint32_t sKH = kb, sKL = kb + 64 * VP, sVH = kb + 128 * VP, sVL = kb + 192 * VP;

        float S[8][4];
        #pragma unroll
        for (int nt = 0; nt < 8; nt++)
            #pragma unroll
            for (int q = 0; q < 4; q++) S[nt][q] = 0.f;
        #pragma unroll
        for (int j = 0; j < 8; j++) {
            #pragma unroll
            for (int g = 0; g < 4; g++) {
                uint32_t bh0, bh1, bh2, bh3, bl0, bl1, bl2, bl3;
                uint32_t adh = sbase + (uint32_t)(sKH + (g * 16 + b_n) * VP + j * 16 + b_k8) * 2;
                LDSM4(bh0, bh1, bh2, bh3, adh);
                uint32_t adl = sbase + (uint32_t)(sKL + (g * 16 + b_n) * VP + j * 16 + b_k8) * 2;
                LDSM4(bl0, bl1, bl2, bl3, adl);
                MMA16816(S[2*g],   qh[j][0], qh[j][1], qh[j][2], qh[j][3], bh0, bh1);
                MMA16816(S[2*g],   qh[j][0], qh[j][1], qh[j][2], qh[j][3], bl0, bl1);
                MMA16816(S[2*g],   ql[j][0], ql[j][1], ql[j][2], ql[j][3], bh0, bh1);
                MMA16816(S[2*g+1], qh[j][0], qh[j][1], qh[j][2], qh[j][3], bh2, bh3);
                MMA16816(S[2*g+1], qh[j][0], qh[j][1], qh[j][2], qh[j][3], bl2, bl3);
                MMA16816(S[2*g+1], ql[j][0], ql[j][1], ql[j][2], ql[j][3], bh2, bh3);
            }
        }

        #pragma unroll
        for (int rr = 0; rr < 2; rr++) {
            int c0 = rr * 2;
            float mx = -1e30f;
            #pragma unroll
            for (int nt = 0; nt < 8; nt++)
                mx = fmaxf(mx, fmaxf(S[nt][c0], S[nt][c0 + 1]));
            mx = fmaxf(mx, __shfl_xor_sync(0xffffffffu, mx, 1));
            mx = fmaxf(mx, __shfl_xor_sync(0xffffffffu, mx, 2));
            if (mx > m_[rr]) {
                float corr = exp2f(m_[rr] - mx);
                m_[rr] = mx;
                l_[rr] *= corr;
                #pragma unroll
                for (int nt = 0; nt < 16; nt++) {
                    o[nt][c0] *= corr; o[nt][c0 + 1] *= corr;
                }
            }
            float mn = m_[rr];
            float sum = 0.f;
            #pragma unroll
            for (int nt = 0; nt < 8; nt++) {
                float p0 = exp2f(S[nt][c0] - mn);
                float p1 = exp2f(S[nt][c0 + 1] - mn);
                S[nt][c0] = p0; S[nt][c0 + 1] = p1;
                sum += p0 + p1;
            }
            sum += __shfl_xor_sync(0xffffffffu, sum, 1);
            sum += __shfl_xor_sync(0xffffffffu, sum, 2);
            l_[rr] += sum;
        }

        uint32_t ph[4][4], pl[4][4];
        #pragma unroll
        for (int jp = 0; jp < 4; jp++) {
            #pragma unroll
            for (int q = 0; q < 4; q++) {
                int nt = 2 * jp + (q >> 1);
                int c0 = (q & 1) * 2;
                float x = S[nt][c0], y = S[nt][c0 + 1];
                __nv_bfloat16 hx = __float2bfloat16_rn(x);
                __nv_bfloat16 hy = __float2bfloat16_rn(y);
                ph[jp][q] = (unsigned)__bfloat16_as_ushort(hx) |
                            ((unsigned)__bfloat16_as_ushort(hy) << 16);
                pl[jp][q] = pack_bf2(x - __bfloat162float(hx), y - __bfloat162float(hy));
            }
        }

        #pragma unroll
        for (int jp = 0; jp < 4; jp++) {
            #pragma unroll
            for (int g = 0; g < 8; g++) {
                uint32_t vh0, vh1, vh2, vh3, vl0, vl1, vl2, vl3;
                uint32_t adh = sbase + (uint32_t)(sVH + (jp * 16 + v_r) * VP + g * 16 + v_n8) * 2;
                LDSM4T(vh0, vh1, vh2, vh3, adh);
                uint32_t adl = sbase + (uint32_t)(sVL + (jp * 16 + v_r) * VP + g * 16 + v_n8) * 2;
                LDSM4T(vl0, vl1, vl2, vl3, adl);
                MMA16816(o[2*g],   ph[jp][0], ph[jp][1], ph[jp][2], ph[jp][3], vh0, vh1);
                MMA16816(o[2*g],   ph[jp][0], ph[jp][1], ph[jp][2], ph[jp][3], vl0, vl1);
                MMA16816(o[2*g],   pl[jp][0], pl[jp][1], pl[jp][2], pl[jp][3], vh0, vh1);
                MMA16816(o[2*g+1], ph[jp][0], ph[jp][1], ph[jp][2], ph[jp][3], vh2, vh3);
                MMA16816(o[2*g+1], ph[jp][0], ph[jp][1], ph[jp][2], ph[jp][3], vl2, vl3);
                MMA16816(o[2*g+1], pl[jp][0], pl[jp][1], pl[jp][2], pl[jp][3], vh2, vh3);
            }
        }

        cur = (cur == 2) ? 0 : cur + 1;
        nx2 = (nx2 == 2) ? 0 : nx2 + 1;
    }

    // ---- epilogue: write unnormalized partials (o, m, l) ----
    float* po = &g_po[split][bh][qt][0];
    #pragma unroll
    for (int rr = 0; rr < 2; rr++) {
        int srow = wid * 16 + (lid >> 2) + rr * 8;
        if ((lid & 3) == 0) {
            g_pm[split][bh][qt][srow] = m_[rr];
            g_pl[split][bh][qt][srow] = l_[rr];
        }
        float* pr = po + (size_t)srow * 128 + (lid & 3) * 2;
        #pragma unroll
        for (int nt = 0; nt < 16; nt++) {
            *(float2*)&pr[nt * 8] = make_float2(o[nt][rr * 2], o[nt][rr * 2 + 1]);
        }
    }
}

// ---------------- launch ----------------
extern "C" void kernel_launch(void* const* d_in, const int* in_sizes, int n_in,
                              void* d_out, int out_size) {
    const float* query = (const float*)d_in[0];
    const float* key   = (const float*)d_in[1];
    const float* value = (const float*)d_in[2];
    const float* q_w   = (const float*)d_in[3];
    const float* q_b   = (const float*)d_in[4];
    const float* k_w   = (const float*)d_in[5];
    const float* k_b   = (const float*)d_in[6];
    const float* v_w   = (const float*)d_in[7];
    const float* v_b   = (const float*)d_in[8];
    const float* ln_g  = (const float*)d_in[9];
    const float* ln_b  = (const float*)d_in[10];
    const float* out_w = (const float*)d_in[11];
    const float* out_b = (const float*)d_in[12];

    cudaFuncSetAttribute(attn_mma, cudaFuncAttributeMaxDynamicSharedMemorySize, ATTN_SMEM);
    cudaFuncSetAttribute(gemm_qkv, cudaFuncAttributeMaxDynamicSharedMemorySize, GEMM_SMEM);
    cudaFuncSetAttribute(gemm_out, cudaFuncAttributeMaxDynamicSharedMemorySize, GEMM_SMEM);

    // weight prep (1 launch) + final reduce
    prep_w<<<dim3(256, 4), 256>>>((const float4*)q_w, (const float4*)k_w,
                                  (const float4*)v_w, (const float4*)out_w);
    absmean_final<<<4, 256>>>();

    // activation quants (warp-per-token), then projections (1 launch)
    quant_rms<<<dim3(NTOK / 8, 3), 256>>>(query, key, value);
    gemm_qkv<<<384, 256, GEMM_SMEM>>>(q_b, k_b, v_b);

    // attention: split-KV x4 (1024 CTAs); combine fused into ln_quant
    attn_mma<<<dim3(SEQ / 128, 16, NSPLIT), 256, ATTN_SMEM>>>();

    // fused combine + layernorm + quant, then final bitlinear
    ln_quant<<<NTOK / 8, 256>>>(ln_g, ln_b);
    gemm_out<<<256, 256, GEMM_SMEM>>>(out_b, (float*)d_out);
}